// round 1
// baseline (speedup 1.0000x reference)
#include <cuda_runtime.h>
#include <cstdint>

#define B_   2
#define L_   2048
#define DIM_ 3072
#define H_   24
#define HD_  128
#define TOK  (B_ * L_)          // 4096
#define N_QKV (3 * DIM_)        // 9216

// ---------------- scratch (device globals — no allocation allowed) ----------
__device__ float g_q[(size_t)B_ * H_ * L_ * HD_];
__device__ float g_k[(size_t)B_ * H_ * L_ * HD_];
__device__ float g_v[(size_t)B_ * H_ * L_ * HD_];
__device__ float g_o[(size_t)TOK * DIM_];

// ============================================================================
// GEMM: C[M,N] = A[M,K] @ W[N,K]^T + bias[N]
// BM=128, BN=64, BK=16, 256 threads, 8x4 microtile per thread.
// MODE 0: A = g_o (proj),  C = param out (plain row-major [M,N])
// MODE 1: A = param (x),   scatter epilogue into g_q/g_k/g_v as [B,H,L,D]
// ============================================================================
template <int MODE>
__global__ __launch_bounds__(256) void gemm_kernel(
    const float* __restrict__ A_in, const float* __restrict__ W,
    const float* __restrict__ bias, float* __restrict__ Cout,
    int M, int N, int K)
{
    __shared__ float As[16][132];
    __shared__ float Bs[16][68];

    const float* A = (MODE == 0) ? g_o : A_in;

    int tid = threadIdx.x;
    int tx = tid & 15;        // 0..15  -> 4 N-cols (tx*4..)
    int ty = tid >> 4;        // 0..15  -> 8 M-rows (ty*8..)
    int col0 = blockIdx.x * 64;
    int row0 = blockIdx.y * 128;

    float acc[8][4];
#pragma unroll
    for (int i = 0; i < 8; i++)
#pragma unroll
        for (int j = 0; j < 4; j++) acc[i][j] = 0.f;

    int lm = tid >> 2;          // 0..63
    int lk = (tid & 3) * 4;     // 0,4,8,12

    for (int kt = 0; kt < K; kt += 16) {
        // A tile: 128 x 16 (two passes of 64 rows)
#pragma unroll
        for (int p = 0; p < 2; p++) {
            int m = lm + p * 64;
            float4 v = *reinterpret_cast<const float4*>(
                &A[(size_t)(row0 + m) * K + kt + lk]);
            As[lk + 0][m] = v.x; As[lk + 1][m] = v.y;
            As[lk + 2][m] = v.z; As[lk + 3][m] = v.w;
        }
        // B tile: 64 x 16
        {
            int n = lm;
            float4 v = *reinterpret_cast<const float4*>(
                &W[(size_t)(col0 + n) * K + kt + lk]);
            Bs[lk + 0][n] = v.x; Bs[lk + 1][n] = v.y;
            Bs[lk + 2][n] = v.z; Bs[lk + 3][n] = v.w;
        }
        __syncthreads();

#pragma unroll
        for (int kk = 0; kk < 16; kk++) {
            float4 a0 = *reinterpret_cast<float4*>(&As[kk][ty * 8]);
            float4 a1 = *reinterpret_cast<float4*>(&As[kk][ty * 8 + 4]);
            float4 b0 = *reinterpret_cast<float4*>(&Bs[kk][tx * 4]);
            float a[8] = {a0.x, a0.y, a0.z, a0.w, a1.x, a1.y, a1.z, a1.w};
            float b[4] = {b0.x, b0.y, b0.z, b0.w};
#pragma unroll
            for (int i = 0; i < 8; i++)
#pragma unroll
                for (int j = 0; j < 4; j++)
                    acc[i][j] = fmaf(a[i], b[j], acc[i][j]);
        }
        __syncthreads();
    }

    // epilogue
    float bv[4];
#pragma unroll
    for (int j = 0; j < 4; j++) bv[j] = bias[col0 + tx * 4 + j];

#pragma unroll
    for (int i = 0; i < 8; i++) {
        int m = row0 + ty * 8 + i;
#pragma unroll
        for (int j = 0; j < 4; j++) {
            int n = col0 + tx * 4 + j;
            float val = acc[i][j] + bv[j];
            if (MODE == 0) {
                Cout[(size_t)m * N + n] = val;
            } else {
                int s   = n / DIM_;
                int rem = n - s * DIM_;
                int h   = rem >> 7;       // /128
                int d   = rem & 127;
                int b   = m >> 11;        // /2048
                int l   = m & 2047;
                size_t dst = ((size_t)(b * H_ + h) * L_ + l) * HD_ + d;
                if (s == 0)      g_q[dst] = val;
                else if (s == 1) g_k[dst] = val;
                else             g_v[dst] = val;
            }
        }
    }
}

// ============================================================================
// RMSNorm + RoPE, one warp per (b,h,l) row of 128. First half = q, second = k.
// pe layout: [L, 64, 2, 2] -> offset l*256 + i*4 + r*2 + c
// ============================================================================
__global__ __launch_bounds__(256) void rmsrope_kernel(
    const float* __restrict__ pe,
    const float* __restrict__ q_scale,
    const float* __restrict__ k_scale)
{
    int gw   = (blockIdx.x * blockDim.x + threadIdx.x) >> 5;
    int lane = threadIdx.x & 31;
    const int total = B_ * H_ * L_;
    bool is_k = gw >= total;
    int row = is_k ? gw - total : gw;
    float* ptr = (is_k ? g_k : g_q) + (size_t)row * HD_;
    const float* scale = is_k ? k_scale : q_scale;
    int l = row & (L_ - 1);

    float4 v = *reinterpret_cast<float4*>(&ptr[lane * 4]);
    float ss = v.x * v.x + v.y * v.y + v.z * v.z + v.w * v.w;
#pragma unroll
    for (int o = 16; o; o >>= 1) ss += __shfl_xor_sync(~0u, ss, o);
    float rrms = rsqrtf(ss * (1.0f / 128.0f) + 1e-6f);

    float4 sc = *reinterpret_cast<const float4*>(&scale[lane * 4]);
    v.x *= rrms * sc.x; v.y *= rrms * sc.y;
    v.z *= rrms * sc.z; v.w *= rrms * sc.w;

    const float* pe_l = pe + (size_t)l * 256;
    int i0 = lane * 2;       // pair (v.x, v.y)
    float4 m0 = *reinterpret_cast<const float4*>(&pe_l[i0 * 4]);
    float o0 = m0.x * v.x + m0.y * v.y;
    float o1 = m0.z * v.x + m0.w * v.y;
    int i1 = i0 + 1;         // pair (v.z, v.w)
    float4 m1 = *reinterpret_cast<const float4*>(&pe_l[i1 * 4]);
    float o2 = m1.x * v.z + m1.y * v.w;
    float o3 = m1.z * v.z + m1.w * v.w;

    float4 out = make_float4(o0, o1, o2, o3);
    *reinterpret_cast<float4*>(&ptr[lane * 4]) = out;
}

// ============================================================================
// Flash attention, fp32. 64 q-rows x 64 kv-rows tiles, D=128, 256 threads.
// smem: Qs/Ks/Vs [64][132], Ps [64][68], m/l/alpha [64].
// Thread (ty=tid/16, tx=tid%16):
//   S microtile: rows ty*4+i, cols tx+16*j
//   O microtile: rows ty*4+i, cols tx*8..tx*8+7
// ============================================================================
#define QSTRIDE 132
#define PSTRIDE 68

__global__ __launch_bounds__(256) void attn_kernel()
{
    extern __shared__ float sm[];
    float* Qs    = sm;                       // 64*132
    float* Ks    = Qs + 64 * QSTRIDE;
    float* Vs    = Ks + 64 * QSTRIDE;
    float* Ps    = Vs + 64 * QSTRIDE;        // 64*68
    float* sm_m  = Ps + 64 * PSTRIDE;
    float* sm_l  = sm_m + 64;
    float* sm_al = sm_l + 64;

    int tid = threadIdx.x;
    int tx = tid & 15, ty = tid >> 4;
    int q0 = blockIdx.x * 64;
    int h  = blockIdx.y;
    int b  = blockIdx.z;

    const size_t head_off = (size_t)(b * H_ + h) * L_ * HD_;
    const float* qg = g_q + head_off;
    const float* kg = g_k + head_off;
    const float* vg = g_v + head_off;

    // load Q tile
#pragma unroll
    for (int p = 0; p < 8; p++) {
        int fi = tid + 256 * p;             // 0..2047
        int r = fi >> 5, d4 = (fi & 31) * 4;
        *reinterpret_cast<float4*>(&Qs[r * QSTRIDE + d4]) =
            *reinterpret_cast<const float4*>(&qg[(size_t)(q0 + r) * HD_ + d4]);
    }
    if (tid < 64) { sm_m[tid] = -1e30f; sm_l[tid] = 0.f; }

    float acc[4][8];
#pragma unroll
    for (int i = 0; i < 4; i++)
#pragma unroll
        for (int j = 0; j < 8; j++) acc[i][j] = 0.f;
    __syncthreads();

    for (int kt = 0; kt < L_; kt += 64) {
        // load K,V tiles
#pragma unroll
        for (int p = 0; p < 8; p++) {
            int fi = tid + 256 * p;
            int r = fi >> 5, d4 = (fi & 31) * 4;
            *reinterpret_cast<float4*>(&Ks[r * QSTRIDE + d4]) =
                *reinterpret_cast<const float4*>(&kg[(size_t)(kt + r) * HD_ + d4]);
            *reinterpret_cast<float4*>(&Vs[r * QSTRIDE + d4]) =
                *reinterpret_cast<const float4*>(&vg[(size_t)(kt + r) * HD_ + d4]);
        }
        __syncthreads();

        // S = Q K^T (scaled)
        float s[4][4];
#pragma unroll
        for (int i = 0; i < 4; i++)
#pragma unroll
            for (int j = 0; j < 4; j++) s[i][j] = 0.f;

#pragma unroll 8
        for (int kk = 0; kk < 128; kk += 4) {
            float4 qv[4], kv[4];
#pragma unroll
            for (int i = 0; i < 4; i++)
                qv[i] = *reinterpret_cast<float4*>(&Qs[(ty * 4 + i) * QSTRIDE + kk]);
#pragma unroll
            for (int j = 0; j < 4; j++)
                kv[j] = *reinterpret_cast<float4*>(&Ks[(tx + 16 * j) * QSTRIDE + kk]);
#pragma unroll
            for (int i = 0; i < 4; i++)
#pragma unroll
                for (int j = 0; j < 4; j++) {
                    s[i][j] = fmaf(qv[i].x, kv[j].x, s[i][j]);
                    s[i][j] = fmaf(qv[i].y, kv[j].y, s[i][j]);
                    s[i][j] = fmaf(qv[i].z, kv[j].z, s[i][j]);
                    s[i][j] = fmaf(qv[i].w, kv[j].w, s[i][j]);
                }
        }
        const float scl = 0.08838834764831845f;   // 1/sqrt(128)
#pragma unroll
        for (int i = 0; i < 4; i++)
#pragma unroll
            for (int j = 0; j < 4; j++)
                Ps[(ty * 4 + i) * PSTRIDE + tx + 16 * j] = s[i][j] * scl;
        __syncthreads();

        // online softmax: warp w owns rows 8w..8w+7
        {
            int w = tid >> 5, lane = tid & 31;
#pragma unroll
            for (int rr = 0; rr < 8; rr++) {
                int r = w * 8 + rr;
                float s1 = Ps[r * PSTRIDE + lane];
                float s2 = Ps[r * PSTRIDE + lane + 32];
                float mx = fmaxf(s1, s2);
#pragma unroll
                for (int o = 16; o; o >>= 1)
                    mx = fmaxf(mx, __shfl_xor_sync(~0u, mx, o));
                float mold = sm_m[r];
                float mnew = fmaxf(mold, mx);
                float p1 = __expf(s1 - mnew);
                float p2 = __expf(s2 - mnew);
                Ps[r * PSTRIDE + lane] = p1;
                Ps[r * PSTRIDE + lane + 32] = p2;
                float sum = p1 + p2;
#pragma unroll
                for (int o = 16; o; o >>= 1)
                    sum += __shfl_xor_sync(~0u, sum, o);
                float al = __expf(mold - mnew);
                if (lane == 0) {
                    sm_m[r] = mnew;
                    sm_l[r] = sm_l[r] * al + sum;
                    sm_al[r] = al;
                }
            }
        }
        __syncthreads();

        // O = O*alpha + P V
        float al[4];
#pragma unroll
        for (int i = 0; i < 4; i++) al[i] = sm_al[ty * 4 + i];
#pragma unroll
        for (int i = 0; i < 4; i++)
#pragma unroll
            for (int j = 0; j < 8; j++) acc[i][j] *= al[i];

#pragma unroll 8
        for (int j = 0; j < 64; j++) {
            float p[4];
#pragma unroll
            for (int i = 0; i < 4; i++) p[i] = Ps[(ty * 4 + i) * PSTRIDE + j];
            float4 v0 = *reinterpret_cast<float4*>(&Vs[j * QSTRIDE + tx * 8]);
            float4 v1 = *reinterpret_cast<float4*>(&Vs[j * QSTRIDE + tx * 8 + 4]);
#pragma unroll
            for (int i = 0; i < 4; i++) {
                acc[i][0] = fmaf(p[i], v0.x, acc[i][0]);
                acc[i][1] = fmaf(p[i], v0.y, acc[i][1]);
                acc[i][2] = fmaf(p[i], v0.z, acc[i][2]);
                acc[i][3] = fmaf(p[i], v0.w, acc[i][3]);
                acc[i][4] = fmaf(p[i], v1.x, acc[i][4]);
                acc[i][5] = fmaf(p[i], v1.y, acc[i][5]);
                acc[i][6] = fmaf(p[i], v1.z, acc[i][6]);
                acc[i][7] = fmaf(p[i], v1.w, acc[i][7]);
            }
        }
        __syncthreads();
    }

    // write out: g_o[(b*L + l)*DIM + h*128 + c]
#pragma unroll
    for (int i = 0; i < 4; i++) {
        int r = ty * 4 + i;
        float inv = 1.0f / sm_l[r];
        int l = q0 + r;
        float* og = g_o + ((size_t)(b * L_ + l)) * DIM_ + h * HD_ + tx * 8;
        float4 o0 = make_float4(acc[i][0] * inv, acc[i][1] * inv,
                                acc[i][2] * inv, acc[i][3] * inv);
        float4 o1 = make_float4(acc[i][4] * inv, acc[i][5] * inv,
                                acc[i][6] * inv, acc[i][7] * inv);
        *reinterpret_cast<float4*>(&og[0]) = o0;
        *reinterpret_cast<float4*>(&og[4]) = o1;
    }
}

// ============================================================================
extern "C" void kernel_launch(void* const* d_in, const int* in_sizes, int n_in,
                              void* d_out, int out_size)
{
    const float* x       = (const float*)d_in[0];
    const float* pe      = (const float*)d_in[1];
    const float* Wqkv    = (const float*)d_in[2];
    const float* bqkv    = (const float*)d_in[3];
    const float* q_scale = (const float*)d_in[4];
    const float* k_scale = (const float*)d_in[5];
    const float* Wproj   = (const float*)d_in[6];
    const float* bproj   = (const float*)d_in[7];
    float* out = (float*)d_out;

    // 1) QKV GEMM + scatter
    {
        dim3 grid(N_QKV / 64, TOK / 128);
        gemm_kernel<1><<<grid, 256>>>(x, Wqkv, bqkv, nullptr, TOK, N_QKV, DIM_);
    }
    // 2) RMSNorm + RoPE on q and k
    {
        int rows = 2 * B_ * H_ * L_;           // 196608 warps
        int blocks = rows / 8;                 // 8 warps per block
        rmsrope_kernel<<<blocks, 256>>>(pe, q_scale, k_scale);
    }
    // 3) flash attention
    {
        size_t smem = (3 * 64 * QSTRIDE + 64 * PSTRIDE + 3 * 64) * sizeof(float);
        cudaFuncSetAttribute(attn_kernel,
                             cudaFuncAttributeMaxDynamicSharedMemorySize,
                             (int)smem);
        dim3 grid(L_ / 64, H_, B_);
        attn_kernel<<<grid, 256, smem>>>();
    }
    // 4) output projection
    {
        dim3 grid(DIM_ / 64, TOK / 128);
        gemm_kernel<0><<<grid, 256>>>(nullptr, Wproj, bproj, out, TOK, DIM_, DIM_);
    }
}

// round 7
// speedup vs baseline: 1.6336x; 1.6336x over previous
#include <cuda_runtime.h>
#include <cstdint>

#define B_   2
#define L_   2048
#define DIM_ 3072
#define H_   24
#define HD_  128
#define TOK  (B_ * L_)          // 4096
#define N_QKV (3 * DIM_)        // 9216

// ---------------- scratch (device globals — no allocation allowed) ----------
__device__ float g_q[(size_t)B_ * H_ * L_ * HD_];
__device__ float g_k[(size_t)B_ * H_ * L_ * HD_];
__device__ float g_v[(size_t)B_ * H_ * L_ * HD_];
__device__ float g_o[(size_t)TOK * DIM_];

// ============================================================================
// helpers
// ============================================================================
__device__ __forceinline__ uint32_t f2tf(float f) {
    uint32_t r; asm("cvt.rna.tf32.f32 %0, %1;" : "=r"(r) : "f"(f)); return r;
}
__device__ __forceinline__ void mma_tf32(float* d, const uint32_t* a,
                                         uint32_t b0, uint32_t b1) {
    asm volatile(
        "mma.sync.aligned.m16n8k8.row.col.f32.tf32.tf32.f32 "
        "{%0,%1,%2,%3}, {%4,%5,%6,%7}, {%8,%9}, {%0,%1,%2,%3};"
        : "+f"(d[0]), "+f"(d[1]), "+f"(d[2]), "+f"(d[3])
        : "r"(a[0]), "r"(a[1]), "r"(a[2]), "r"(a[3]), "r"(b0), "r"(b1));
}

// ============================================================================
// tf32 mma.sync GEMM: C[M,N] = A[M,K] @ W[N,K]^T + bias[N]
// BM=256, BN=128, BK=16. 256 threads = 8 warps (4m x 2n), warp tile 64x64.
// Fragments: m16n8k8. SMEM rows stride 20 floats (conflict-free frag loads).
// MODE 0: A = g_o, C -> Cout row-major [M,N]
// MODE 1: A = A_in (x), scatter into g_q/g_k/g_v as [B,H,L,D]
// ============================================================================
#define ASTRIDE 20
#define A_FLOATS (256 * ASTRIDE)   // per stage
#define B_FLOATS (128 * ASTRIDE)
#define GEMM_SMEM ((2 * A_FLOATS + 2 * B_FLOATS) * 4)   // 61440 bytes

template <int MODE>
__global__ __launch_bounds__(256, 1) void gemm_mma(
    const float* __restrict__ A_in, const float* __restrict__ W,
    const float* __restrict__ bias, float* __restrict__ Cout,
    int M, int N, int K)
{
    extern __shared__ float dsm[];
    float* As = dsm;                       // [2][256][20]
    float* Bs = dsm + 2 * A_FLOATS;        // [2][128][20]

    const float* A = (MODE == 0) ? g_o : A_in;

    const int tid = threadIdx.x;
    const int wid = tid >> 5, lane = tid & 31;
    const int wm = wid >> 1, wn = wid & 1;
    const int qr = lane >> 2, c4 = lane & 3;
    const int row0 = blockIdx.y * 256;
    const int col0 = blockIdx.x * 128;
    const int NSTEP = K / 16;

    const int lrow = tid >> 2;      // 0..63
    const int lc4  = (tid & 3) * 4; // k offset 0,4,8,12

    float acc[4][8][4];
#pragma unroll
    for (int mm = 0; mm < 4; mm++)
#pragma unroll
        for (int nn = 0; nn < 8; nn++)
#pragma unroll
            for (int q = 0; q < 4; q++) acc[mm][nn][q] = 0.f;

    // ---- prologue: stage 0 ----
#pragma unroll
    for (int p = 0; p < 4; p++) {
        int r = lrow + 64 * p;
        float4 v = *reinterpret_cast<const float4*>(&A[(size_t)(row0 + r) * K + lc4]);
        float4 t = make_float4(__uint_as_float(f2tf(v.x)), __uint_as_float(f2tf(v.y)),
                               __uint_as_float(f2tf(v.z)), __uint_as_float(f2tf(v.w)));
        *reinterpret_cast<float4*>(&As[r * ASTRIDE + lc4]) = t;
    }
#pragma unroll
    for (int p = 0; p < 2; p++) {
        int n = lrow + 64 * p;
        float4 v = *reinterpret_cast<const float4*>(&W[(size_t)(col0 + n) * K + lc4]);
        float4 t = make_float4(__uint_as_float(f2tf(v.x)), __uint_as_float(f2tf(v.y)),
                               __uint_as_float(f2tf(v.z)), __uint_as_float(f2tf(v.w)));
        *reinterpret_cast<float4*>(&Bs[n * ASTRIDE + lc4]) = t;
    }
    __syncthreads();

    int buf = 0;
    for (int step = 0; step < NSTEP; ++step) {
        const bool more = (step + 1) < NSTEP;
        const int kt = (step + 1) * 16;

        // prefetch next tile into registers
        float4 pa[4], pb[2];
        if (more) {
#pragma unroll
            for (int p = 0; p < 4; p++) {
                int r = lrow + 64 * p;
                pa[p] = *reinterpret_cast<const float4*>(
                    &A[(size_t)(row0 + r) * K + kt + lc4]);
            }
#pragma unroll
            for (int p = 0; p < 2; p++) {
                int n = lrow + 64 * p;
                pb[p] = *reinterpret_cast<const float4*>(
                    &W[(size_t)(col0 + n) * K + kt + lc4]);
            }
        }

        // compute on current buffer
        {
            const float* Ab = As + buf * A_FLOATS;
            const float* Bb = Bs + buf * B_FLOATS;
#pragma unroll
            for (int ks = 0; ks < 2; ks++) {
                const int kb = ks * 8 + c4;
                uint32_t a[4][4];
#pragma unroll
                for (int mm = 0; mm < 4; mm++) {
                    int r = wm * 64 + mm * 16 + qr;
                    a[mm][0] = __float_as_uint(Ab[r * ASTRIDE + kb]);
                    a[mm][1] = __float_as_uint(Ab[(r + 8) * ASTRIDE + kb]);
                    a[mm][2] = __float_as_uint(Ab[r * ASTRIDE + kb + 4]);
                    a[mm][3] = __float_as_uint(Ab[(r + 8) * ASTRIDE + kb + 4]);
                }
#pragma unroll
                for (int nn = 0; nn < 8; nn++) {
                    int n = wn * 64 + nn * 8 + qr;
                    uint32_t b0 = __float_as_uint(Bb[n * ASTRIDE + kb]);
                    uint32_t b1 = __float_as_uint(Bb[n * ASTRIDE + kb + 4]);
#pragma unroll
                    for (int mm = 0; mm < 4; mm++)
                        mma_tf32(acc[mm][nn], a[mm], b0, b1);
                }
            }
        }

        // store next tile
        if (more) {
            int nbuf = buf ^ 1;
            float* Ab = As + nbuf * A_FLOATS;
            float* Bb = Bs + nbuf * B_FLOATS;
#pragma unroll
            for (int p = 0; p < 4; p++) {
                int r = lrow + 64 * p;
                float4 v = pa[p];
                float4 t = make_float4(__uint_as_float(f2tf(v.x)), __uint_as_float(f2tf(v.y)),
                                       __uint_as_float(f2tf(v.z)), __uint_as_float(f2tf(v.w)));
                *reinterpret_cast<float4*>(&Ab[r * ASTRIDE + lc4]) = t;
            }
#pragma unroll
            for (int p = 0; p < 2; p++) {
                int n = lrow + 64 * p;
                float4 v = pb[p];
                float4 t = make_float4(__uint_as_float(f2tf(v.x)), __uint_as_float(f2tf(v.y)),
                                       __uint_as_float(f2tf(v.z)), __uint_as_float(f2tf(v.w)));
                *reinterpret_cast<float4*>(&Bb[n * ASTRIDE + lc4]) = t;
            }
            __syncthreads();
            buf = nbuf;
        }
    }

    // ---- epilogue: registers -> gmem (float2 per c-pair) ----
#pragma unroll
    for (int nn = 0; nn < 8; nn++) {
        const int n = col0 + wn * 64 + nn * 8 + c4 * 2;
        const float b0 = bias[n], b1 = bias[n + 1];
#pragma unroll
        for (int mm = 0; mm < 4; mm++) {
            const int mrow = row0 + wm * 64 + mm * 16 + qr;
#pragma unroll
            for (int half = 0; half < 2; half++) {
                const int m = mrow + half * 8;
                float2 v = make_float2(acc[mm][nn][half * 2] + b0,
                                       acc[mm][nn][half * 2 + 1] + b1);
                if (MODE == 0) {
                    *reinterpret_cast<float2*>(&Cout[(size_t)m * N + n]) = v;
                } else {
                    int s   = n / DIM_;
                    int rem = n - s * DIM_;
                    int h   = rem >> 7;
                    int d   = rem & 127;
                    int b   = m >> 11;
                    int l   = m & 2047;
                    float* base = (s == 0) ? g_q : (s == 1) ? g_k : g_v;
                    *reinterpret_cast<float2*>(
                        &base[((size_t)(b * H_ + h) * L_ + l) * HD_ + d]) = v;
                }
            }
        }
    }
}

// ============================================================================
// RMSNorm + RoPE (unchanged)
// ============================================================================
__global__ __launch_bounds__(256) void rmsrope_kernel(
    const float* __restrict__ pe,
    const float* __restrict__ q_scale,
    const float* __restrict__ k_scale)
{
    int gw   = (blockIdx.x * blockDim.x + threadIdx.x) >> 5;
    int lane = threadIdx.x & 31;
    const int total = B_ * H_ * L_;
    bool is_k = gw >= total;
    int row = is_k ? gw - total : gw;
    float* ptr = (is_k ? g_k : g_q) + (size_t)row * HD_;
    const float* scale = is_k ? k_scale : q_scale;
    int l = row & (L_ - 1);

    float4 v = *reinterpret_cast<float4*>(&ptr[lane * 4]);
    float ss = v.x * v.x + v.y * v.y + v.z * v.z + v.w * v.w;
#pragma unroll
    for (int o = 16; o; o >>= 1) ss += __shfl_xor_sync(~0u, ss, o);
    float rrms = rsqrtf(ss * (1.0f / 128.0f) + 1e-6f);

    float4 sc = *reinterpret_cast<const float4*>(&scale[lane * 4]);
    v.x *= rrms * sc.x; v.y *= rrms * sc.y;
    v.z *= rrms * sc.z; v.w *= rrms * sc.w;

    const float* pe_l = pe + (size_t)l * 256;
    int i0 = lane * 2;
    float4 m0 = *reinterpret_cast<const float4*>(&pe_l[i0 * 4]);
    float o0 = m0.x * v.x + m0.y * v.y;
    float o1 = m0.z * v.x + m0.w * v.y;
    int i1 = i0 + 1;
    float4 m1 = *reinterpret_cast<const float4*>(&pe_l[i1 * 4]);
    float o2 = m1.x * v.z + m1.y * v.w;
    float o3 = m1.z * v.z + m1.w * v.w;

    *reinterpret_cast<float4*>(&ptr[lane * 4]) = make_float4(o0, o1, o2, o3);
}

// ============================================================================
// Flash attention fp32 (unchanged)
// ============================================================================
#define QSTRIDE 132
#define PSTRIDE 68

__global__ __launch_bounds__(256) void attn_kernel()
{
    extern __shared__ float sm[];
    float* Qs    = sm;
    float* Ks    = Qs + 64 * QSTRIDE;
    float* Vs    = Ks + 64 * QSTRIDE;
    float* Ps    = Vs + 64 * QSTRIDE;
    float* sm_m  = Ps + 64 * PSTRIDE;
    float* sm_l  = sm_m + 64;
    float* sm_al = sm_l + 64;

    int tid = threadIdx.x;
    int tx = tid & 15, ty = tid >> 4;
    int q0 = blockIdx.x * 64;
    int h  = blockIdx.y;
    int b  = blockIdx.z;

    const size_t head_off = (size_t)(b * H_ + h) * L_ * HD_;
    const float* qg = g_q + head_off;
    const float* kg = g_k + head_off;
    const float* vg = g_v + head_off;

#pragma unroll
    for (int p = 0; p < 8; p++) {
        int fi = tid + 256 * p;
        int r = fi >> 5, d4 = (fi & 31) * 4;
        *reinterpret_cast<float4*>(&Qs[r * QSTRIDE + d4]) =
            *reinterpret_cast<const float4*>(&qg[(size_t)(q0 + r) * HD_ + d4]);
    }
    if (tid < 64) { sm_m[tid] = -1e30f; sm_l[tid] = 0.f; }

    float acc[4][8];
#pragma unroll
    for (int i = 0; i < 4; i++)
#pragma unroll
        for (int j = 0; j < 8; j++) acc[i][j] = 0.f;
    __syncthreads();

    for (int kt = 0; kt < L_; kt += 64) {
#pragma unroll
        for (int p = 0; p < 8; p++) {
            int fi = tid + 256 * p;
            int r = fi >> 5, d4 = (fi & 31) * 4;
            *reinterpret_cast<float4*>(&Ks[r * QSTRIDE + d4]) =
                *reinterpret_cast<const float4*>(&kg[(size_t)(kt + r) * HD_ + d4]);
            *reinterpret_cast<float4*>(&Vs[r * QSTRIDE + d4]) =
                *reinterpret_cast<const float4*>(&vg[(size_t)(kt + r) * HD_ + d4]);
        }
        __syncthreads();

        float s[4][4];
#pragma unroll
        for (int i = 0; i < 4; i++)
#pragma unroll
            for (int j = 0; j < 4; j++) s[i][j] = 0.f;

#pragma unroll 8
        for (int kk = 0; kk < 128; kk += 4) {
            float4 qv[4], kv[4];
#pragma unroll
            for (int i = 0; i < 4; i++)
                qv[i] = *reinterpret_cast<float4*>(&Qs[(ty * 4 + i) * QSTRIDE + kk]);
#pragma unroll
            for (int j = 0; j < 4; j++)
                kv[j] = *reinterpret_cast<float4*>(&Ks[(tx + 16 * j) * QSTRIDE + kk]);
#pragma unroll
            for (int i = 0; i < 4; i++)
#pragma unroll
                for (int j = 0; j < 4; j++) {
                    s[i][j] = fmaf(qv[i].x, kv[j].x, s[i][j]);
                    s[i][j] = fmaf(qv[i].y, kv[j].y, s[i][j]);
                    s[i][j] = fmaf(qv[i].z, kv[j].z, s[i][j]);
                    s[i][j] = fmaf(qv[i].w, kv[j].w, s[i][j]);
                }
        }
        const float scl = 0.08838834764831845f;
#pragma unroll
        for (int i = 0; i < 4; i++)
#pragma unroll
            for (int j = 0; j < 4; j++)
                Ps[(ty * 4 + i) * PSTRIDE + tx + 16 * j] = s[i][j] * scl;
        __syncthreads();

        {
            int w = tid >> 5, lane = tid & 31;
#pragma unroll
            for (int rr = 0; rr < 8; rr++) {
                int r = w * 8 + rr;
                float s1 = Ps[r * PSTRIDE + lane];
                float s2 = Ps[r * PSTRIDE + lane + 32];
                float mx = fmaxf(s1, s2);
#pragma unroll
                for (int o = 16; o; o >>= 1)
                    mx = fmaxf(mx, __shfl_xor_sync(~0u, mx, o));
                float mold = sm_m[r];
                float mnew = fmaxf(mold, mx);
                float p1 = __expf(s1 - mnew);
                float p2 = __expf(s2 - mnew);
                Ps[r * PSTRIDE + lane] = p1;
                Ps[r * PSTRIDE + lane + 32] = p2;
                float sum = p1 + p2;
#pragma unroll
                for (int o = 16; o; o >>= 1)
                    sum += __shfl_xor_sync(~0u, sum, o);
                float al = __expf(mold - mnew);
                if (lane == 0) {
                    sm_m[r] = mnew;
                    sm_l[r] = sm_l[r] * al + sum;
                    sm_al[r] = al;
                }
            }
        }
        __syncthreads();

        float al[4];
#pragma unroll
        for (int i = 0; i < 4; i++) al[i] = sm_al[ty * 4 + i];
#pragma unroll
        for (int i = 0; i < 4; i++)
#pragma unroll
            for (int j = 0; j < 8; j++) acc[i][j] *= al[i];

#pragma unroll 8
        for (int j = 0; j < 64; j++) {
            float p[4];
#pragma unroll
            for (int i = 0; i < 4; i++) p[i] = Ps[(ty * 4 + i) * PSTRIDE + j];
            float4 v0 = *reinterpret_cast<float4*>(&Vs[j * QSTRIDE + tx * 8]);
            float4 v1 = *reinterpret_cast<float4*>(&Vs[j * QSTRIDE + tx * 8 + 4]);
#pragma unroll
            for (int i = 0; i < 4; i++) {
                acc[i][0] = fmaf(p[i], v0.x, acc[i][0]);
                acc[i][1] = fmaf(p[i], v0.y, acc[i][1]);
                acc[i][2] = fmaf(p[i], v0.z, acc[i][2]);
                acc[i][3] = fmaf(p[i], v0.w, acc[i][3]);
                acc[i][4] = fmaf(p[i], v1.x, acc[i][4]);
                acc[i][5] = fmaf(p[i], v1.y, acc[i][5]);
                acc[i][6] = fmaf(p[i], v1.z, acc[i][6]);
                acc[i][7] = fmaf(p[i], v1.w, acc[i][7]);
            }
        }
        __syncthreads();
    }

#pragma unroll
    for (int i = 0; i < 4; i++) {
        int r = ty * 4 + i;
        float inv = 1.0f / sm_l[r];
        int l = q0 + r;
        float* og = g_o + ((size_t)(b * L_ + l)) * DIM_ + h * HD_ + tx * 8;
        *reinterpret_cast<float4*>(&og[0]) =
            make_float4(acc[i][0] * inv, acc[i][1] * inv, acc[i][2] * inv, acc[i][3] * inv);
        *reinterpret_cast<float4*>(&og[4]) =
            make_float4(acc[i][4] * inv, acc[i][5] * inv, acc[i][6] * inv, acc[i][7] * inv);
    }
}

// ============================================================================
extern "C" void kernel_launch(void* const* d_in, const int* in_sizes, int n_in,
                              void* d_out, int out_size)
{
    const float* x       = (const float*)d_in[0];
    const float* pe      = (const float*)d_in[1];
    const float* Wqkv    = (const float*)d_in[2];
    const float* bqkv    = (const float*)d_in[3];
    const float* q_scale = (const float*)d_in[4];
    const float* k_scale = (const float*)d_in[5];
    const float* Wproj   = (const float*)d_in[6];
    const float* bproj   = (const float*)d_in[7];
    float* out = (float*)d_out;

    cudaFuncSetAttribute(gemm_mma<1>, cudaFuncAttributeMaxDynamicSharedMemorySize, GEMM_SMEM);
    cudaFuncSetAttribute(gemm_mma<0>, cudaFuncAttributeMaxDynamicSharedMemorySize, GEMM_SMEM);

    // 1) QKV GEMM (tf32 mma.sync) + scatter
    {
        dim3 grid(N_QKV / 128, TOK / 256);
        gemm_mma<1><<<grid, 256, GEMM_SMEM>>>(x, Wqkv, bqkv, nullptr, TOK, N_QKV, DIM_);
    }
    // 2) RMSNorm + RoPE
    {
        int rows = 2 * B_ * H_ * L_;
        rmsrope_kernel<<<rows / 8, 256>>>(pe, q_scale, k_scale);
    }
    // 3) flash attention (fp32)
    {
        size_t smem = (3 * 64 * QSTRIDE + 64 * PSTRIDE + 3 * 64) * sizeof(float);
        cudaFuncSetAttribute(attn_kernel,
                             cudaFuncAttributeMaxDynamicSharedMemorySize, (int)smem);
        dim3 grid(L_ / 64, H_, B_);
        attn_kernel<<<grid, 256, smem>>>();
    }
    // 4) output projection (tf32 mma.sync)
    {
        dim3 grid(DIM_ / 128, TOK / 256);
        gemm_mma<0><<<grid, 256, GEMM_SMEM>>>(nullptr, Wproj, bproj, out, TOK, DIM_, DIM_);
    }
}

// round 10
// speedup vs baseline: 3.3731x; 2.0649x over previous
#include <cuda_runtime.h>
#include <cstdint>

#define B_   2
#define L_   2048
#define DIM_ 3072
#define H_   24
#define HD_  128
#define TOK  (B_ * L_)          // 4096
#define N_QKV (3 * DIM_)        // 9216

// ---------------- scratch (device globals — no allocation allowed) ----------
__device__ float g_q[(size_t)B_ * H_ * L_ * HD_];
__device__ float g_k[(size_t)B_ * H_ * L_ * HD_];
__device__ float g_v[(size_t)B_ * H_ * L_ * HD_];
__device__ float g_o[(size_t)TOK * DIM_];

// ============================================================================
// helpers
// ============================================================================
__device__ __forceinline__ uint32_t f2tf(float f) {
    uint32_t r; asm("cvt.rna.tf32.f32 %0, %1;" : "=r"(r) : "f"(f)); return r;
}
__device__ __forceinline__ void mma_tf32(float* d, const uint32_t* a,
                                         uint32_t b0, uint32_t b1) {
    asm volatile(
        "mma.sync.aligned.m16n8k8.row.col.f32.tf32.tf32.f32 "
        "{%0,%1,%2,%3}, {%4,%5,%6,%7}, {%8,%9}, {%0,%1,%2,%3};"
        : "+f"(d[0]), "+f"(d[1]), "+f"(d[2]), "+f"(d[3])
        : "r"(a[0]), "r"(a[1]), "r"(a[2]), "r"(a[3]), "r"(b0), "r"(b1));
}
__device__ __forceinline__ uint32_t smem_u32(const void* p) {
    uint32_t a;
    asm("{ .reg .u64 t; cvta.to.shared.u64 t, %1; cvt.u32.u64 %0, t; }"
        : "=r"(a) : "l"(p));
    return a;
}
// ldmatrix x4 (b32 view): matrix m covers rows base+(m&1)*8.., cols k0+(m>>1)*4..
// lane addr: row = base + (l&8)+(l&7), col = k0 + (l>>4)*4
__device__ __forceinline__ void ldsm4(uint32_t* d, uint32_t saddr) {
    asm volatile("ldmatrix.sync.aligned.m8n8.x4.shared.b16 {%0,%1,%2,%3}, [%4];"
        : "=r"(d[0]), "=r"(d[1]), "=r"(d[2]), "=r"(d[3]) : "r"(saddr));
}

// ============================================================================
// tf32 mma.sync GEMM with ldmatrix fragments.
// C[M,N] = A[M,K] @ W[N,K]^T + bias[N]
// BM=256, BN=128, BK=16. 256 threads = 8 warps (4m x 2n), warp tile 64x64.
// SMEM rows stride 20 floats (80B) -> ldmatrix conflict-free.
// MODE 0: A = g_o, C -> Cout row-major. MODE 1: scatter into g_q/g_k/g_v.
// ============================================================================
#define ASTRIDE 20
#define A_FLOATS (256 * ASTRIDE)
#define B_FLOATS (128 * ASTRIDE)
#define GEMM_SMEM ((2 * A_FLOATS + 2 * B_FLOATS) * 4)   // 61440 bytes

template <int MODE>
__global__ __launch_bounds__(256, 1) void gemm_mma(
    const float* __restrict__ A_in, const float* __restrict__ W,
    const float* __restrict__ bias, float* __restrict__ Cout,
    int M, int N, int K)
{
    extern __shared__ float dsm[];
    float* As = dsm;                       // [2][256][20]
    float* Bs = dsm + 2 * A_FLOATS;        // [2][128][20]

    const float* A = (MODE == 0) ? g_o : A_in;

    const int tid = threadIdx.x;
    const int wid = tid >> 5, lane = tid & 31;
    const int wm = wid >> 1, wn = wid & 1;
    const int qr = lane >> 2, c4 = lane & 3;
    const int row0 = blockIdx.y * 256;
    const int col0 = blockIdx.x * 128;
    const int NSTEP = K / 16;

    const int lrow = tid >> 2;
    const int lc4  = (tid & 3) * 4;

    // ldmatrix lane offset (stride 20 floats)
    const int lmr = (lane & 7) + (lane & 8);
    const int lmc = (lane >> 4) << 2;
    const uint32_t lmoff = (uint32_t)(lmr * ASTRIDE + lmc) * 4;
    const uint32_t sA = smem_u32(dsm);
    const uint32_t sB = sA + 2 * A_FLOATS * 4;

    float acc[4][8][4];
#pragma unroll
    for (int mm = 0; mm < 4; mm++)
#pragma unroll
        for (int nn = 0; nn < 8; nn++)
#pragma unroll
            for (int q = 0; q < 4; q++) acc[mm][nn][q] = 0.f;

    // ---- prologue: stage 0 ----
#pragma unroll
    for (int p = 0; p < 4; p++) {
        int r = lrow + 64 * p;
        float4 v = *reinterpret_cast<const float4*>(&A[(size_t)(row0 + r) * K + lc4]);
        float4 t = make_float4(__uint_as_float(f2tf(v.x)), __uint_as_float(f2tf(v.y)),
                               __uint_as_float(f2tf(v.z)), __uint_as_float(f2tf(v.w)));
        *reinterpret_cast<float4*>(&As[r * ASTRIDE + lc4]) = t;
    }
#pragma unroll
    for (int p = 0; p < 2; p++) {
        int n = lrow + 64 * p;
        float4 v = *reinterpret_cast<const float4*>(&W[(size_t)(col0 + n) * K + lc4]);
        float4 t = make_float4(__uint_as_float(f2tf(v.x)), __uint_as_float(f2tf(v.y)),
                               __uint_as_float(f2tf(v.z)), __uint_as_float(f2tf(v.w)));
        *reinterpret_cast<float4*>(&Bs[n * ASTRIDE + lc4]) = t;
    }
    __syncthreads();

    int buf = 0;
    for (int step = 0; step < NSTEP; ++step) {
        const bool more = (step + 1) < NSTEP;
        const int kt = (step + 1) * 16;

        float4 pa[4], pb[2];
        if (more) {
#pragma unroll
            for (int p = 0; p < 4; p++) {
                int r = lrow + 64 * p;
                pa[p] = *reinterpret_cast<const float4*>(
                    &A[(size_t)(row0 + r) * K + kt + lc4]);
            }
#pragma unroll
            for (int p = 0; p < 2; p++) {
                int n = lrow + 64 * p;
                pb[p] = *reinterpret_cast<const float4*>(
                    &W[(size_t)(col0 + n) * K + kt + lc4]);
            }
        }

        // compute on current buffer via ldmatrix
        {
            const uint32_t sAb = sA + (uint32_t)(buf * A_FLOATS) * 4;
            const uint32_t sBb = sB + (uint32_t)(buf * B_FLOATS) * 4;
#pragma unroll
            for (int ks = 0; ks < 2; ks++) {
                uint32_t a[4][4], bb[4][4];
#pragma unroll
                for (int mm = 0; mm < 4; mm++)
                    ldsm4(a[mm], sAb + (uint32_t)((wm * 64 + mm * 16) * ASTRIDE * 4)
                                   + ks * 32 + lmoff);
#pragma unroll
                for (int np = 0; np < 4; np++)
                    ldsm4(bb[np], sBb + (uint32_t)((wn * 64 + np * 16) * ASTRIDE * 4)
                                    + ks * 32 + lmoff);
#pragma unroll
                for (int np = 0; np < 4; np++)
#pragma unroll
                    for (int mm = 0; mm < 4; mm++) {
                        mma_tf32(acc[mm][2 * np],     a[mm], bb[np][0], bb[np][2]);
                        mma_tf32(acc[mm][2 * np + 1], a[mm], bb[np][1], bb[np][3]);
                    }
            }
        }

        if (more) {
            int nbuf = buf ^ 1;
            float* Ab = As + nbuf * A_FLOATS;
            float* Bb = Bs + nbuf * B_FLOATS;
#pragma unroll
            for (int p = 0; p < 4; p++) {
                int r = lrow + 64 * p;
                float4 v = pa[p];
                float4 t = make_float4(__uint_as_float(f2tf(v.x)), __uint_as_float(f2tf(v.y)),
                                       __uint_as_float(f2tf(v.z)), __uint_as_float(f2tf(v.w)));
                *reinterpret_cast<float4*>(&Ab[r * ASTRIDE + lc4]) = t;
            }
#pragma unroll
            for (int p = 0; p < 2; p++) {
                int n = lrow + 64 * p;
                float4 v = pb[p];
                float4 t = make_float4(__uint_as_float(f2tf(v.x)), __uint_as_float(f2tf(v.y)),
                                       __uint_as_float(f2tf(v.z)), __uint_as_float(f2tf(v.w)));
                *reinterpret_cast<float4*>(&Bb[n * ASTRIDE + lc4]) = t;
            }
            __syncthreads();
            buf = nbuf;
        }
    }

    // ---- epilogue ----
#pragma unroll
    for (int nn = 0; nn < 8; nn++) {
        const int n = col0 + wn * 64 + nn * 8 + c4 * 2;
        const float b0 = bias[n], b1 = bias[n + 1];
#pragma unroll
        for (int mm = 0; mm < 4; mm++) {
            const int mrow = row0 + wm * 64 + mm * 16 + qr;
#pragma unroll
            for (int half = 0; half < 2; half++) {
                const int m = mrow + half * 8;
                float2 v = make_float2(acc[mm][nn][half * 2] + b0,
                                       acc[mm][nn][half * 2 + 1] + b1);
                if (MODE == 0) {
                    *reinterpret_cast<float2*>(&Cout[(size_t)m * N + n]) = v;
                } else {
                    int s   = n / DIM_;
                    int rem = n - s * DIM_;
                    int h   = rem >> 7;
                    int d   = rem & 127;
                    int b   = m >> 11;
                    int l   = m & 2047;
                    float* base = (s == 0) ? g_q : (s == 1) ? g_k : g_v;
                    *reinterpret_cast<float2*>(
                        &base[((size_t)(b * H_ + h) * L_ + l) * HD_ + d]) = v;
                }
            }
        }
    }
}

// ============================================================================
// RMSNorm + RoPE (unchanged)
// ============================================================================
__global__ __launch_bounds__(256) void rmsrope_kernel(
    const float* __restrict__ pe,
    const float* __restrict__ q_scale,
    const float* __restrict__ k_scale)
{
    int gw   = (blockIdx.x * blockDim.x + threadIdx.x) >> 5;
    int lane = threadIdx.x & 31;
    const int total = B_ * H_ * L_;
    bool is_k = gw >= total;
    int row = is_k ? gw - total : gw;
    float* ptr = (is_k ? g_k : g_q) + (size_t)row * HD_;
    const float* scale = is_k ? k_scale : q_scale;
    int l = row & (L_ - 1);

    float4 v = *reinterpret_cast<float4*>(&ptr[lane * 4]);
    float ss = v.x * v.x + v.y * v.y + v.z * v.z + v.w * v.w;
#pragma unroll
    for (int o = 16; o; o >>= 1) ss += __shfl_xor_sync(~0u, ss, o);
    float rrms = rsqrtf(ss * (1.0f / 128.0f) + 1e-6f);

    float4 sc = *reinterpret_cast<const float4*>(&scale[lane * 4]);
    v.x *= rrms * sc.x; v.y *= rrms * sc.y;
    v.z *= rrms * sc.z; v.w *= rrms * sc.w;

    const float* pe_l = pe + (size_t)l * 256;
    int i0 = lane * 2;
    float4 m0 = *reinterpret_cast<const float4*>(&pe_l[i0 * 4]);
    float o0 = m0.x * v.x + m0.y * v.y;
    float o1 = m0.z * v.x + m0.w * v.y;
    int i1 = i0 + 1;
    float4 m1 = *reinterpret_cast<const float4*>(&pe_l[i1 * 4]);
    float o2 = m1.x * v.z + m1.y * v.w;
    float o3 = m1.z * v.z + m1.w * v.w;

    *reinterpret_cast<float4*>(&ptr[lane * 4]) = make_float4(o0, o1, o2, o3);
}

// ============================================================================
// Flash attention, tf32 mma.sync.
// q-tile 128, kv-tile 64, 256 threads = 8 warps, warp owns 16 q-rows.
// Q pre-scaled + tf32, A-frags in regs (reused all kv tiles).
// K B-frags via ldmatrix (stride 132). Softmax in registers (lane quads).
// P -> smem (tf32, stride 68, overlaps dead Q region) -> ldmatrix A-frags.
// V B-frags via scalar LDS (conflict-free). O in C-frags (fp32).
// smem: Q/P 128x132 | K 64x132 | V 64x132 = 135168 B. 1 CTA/SM.
// ============================================================================
#define AQ_STR 132
#define AP_STR 68
#define ATTN_SMEM ((128 * AQ_STR + 2 * 64 * AQ_STR) * 4)

__global__ __launch_bounds__(256, 1) void attn_mma()
{
    extern __shared__ float sm[];
    float* Qs = sm;                        // 128 x 132 (later reused as Ps 128 x 68)
    float* Ks = sm + 128 * AQ_STR;         // 64 x 132
    float* Vs = Ks + 64 * AQ_STR;          // 64 x 132

    const int tid = threadIdx.x, w = tid >> 5, lane = tid & 31;
    const int qr = lane >> 2, c4 = lane & 3;
    const int q0 = blockIdx.x * 128;
    const int h = blockIdx.y, b = blockIdx.z;

    const size_t hoff = (size_t)(b * H_ + h) * L_ * HD_;
    const float* qg = g_q + hoff;
    const float* kg = g_k + hoff;
    const float* vg = g_v + hoff;

    const float scl = 0.08838834764831845f;   // 1/sqrt(128), folded into Q

    // ldmatrix lane offsets
    const int lmr = (lane & 7) + (lane & 8);
    const int lmc = (lane >> 4) << 2;
    const uint32_t lmQ = (uint32_t)(lmr * AQ_STR + lmc) * 4;
    const uint32_t lmP = (uint32_t)(lmr * AP_STR + lmc) * 4;
    const uint32_t sQ = smem_u32(sm);
    const uint32_t sK = smem_u32(Ks);

    // ---- load Q (scaled, tf32) ----
#pragma unroll
    for (int p = 0; p < 16; p++) {
        int fi = tid + 256 * p;
        int r = fi >> 5, d4 = (fi & 31) * 4;
        float4 v = *reinterpret_cast<const float4*>(&qg[(size_t)(q0 + r) * HD_ + d4]);
        float4 t = make_float4(__uint_as_float(f2tf(v.x * scl)),
                               __uint_as_float(f2tf(v.y * scl)),
                               __uint_as_float(f2tf(v.z * scl)),
                               __uint_as_float(f2tf(v.w * scl)));
        *reinterpret_cast<float4*>(&Qs[r * AQ_STR + d4]) = t;
    }
    __syncthreads();

    // ---- build Q A-frags (held all loop long) ----
    uint32_t qf[16][4];
    {
        uint32_t qbase = sQ + (uint32_t)(w * 16 * AQ_STR) * 4;
#pragma unroll
        for (int ks = 0; ks < 16; ks++)
            ldsm4(qf[ks], qbase + ks * 32 + lmQ);
    }

    float of[16][4];
#pragma unroll
    for (int nt = 0; nt < 16; nt++)
#pragma unroll
        for (int q = 0; q < 4; q++) of[nt][q] = 0.f;
    float m0 = -1e30f, m1 = -1e30f, l0 = 0.f, l1 = 0.f;

    for (int kt = 0; kt < L_; kt += 64) {
        // ---- load K, V tiles (tf32) ----
#pragma unroll
        for (int p = 0; p < 8; p++) {
            int fi = tid + 256 * p;
            int r = fi >> 5, d4 = (fi & 31) * 4;
            float4 kv = *reinterpret_cast<const float4*>(&kg[(size_t)(kt + r) * HD_ + d4]);
            *reinterpret_cast<float4*>(&Ks[r * AQ_STR + d4]) =
                make_float4(__uint_as_float(f2tf(kv.x)), __uint_as_float(f2tf(kv.y)),
                            __uint_as_float(f2tf(kv.z)), __uint_as_float(f2tf(kv.w)));
            float4 vv = *reinterpret_cast<const float4*>(&vg[(size_t)(kt + r) * HD_ + d4]);
            *reinterpret_cast<float4*>(&Vs[r * AQ_STR + d4]) =
                make_float4(__uint_as_float(f2tf(vv.x)), __uint_as_float(f2tf(vv.y)),
                            __uint_as_float(f2tf(vv.z)), __uint_as_float(f2tf(vv.w)));
        }
        __syncthreads();

        // ---- S = Q K^T ----
        float sacc[8][4];
#pragma unroll
        for (int nn = 0; nn < 8; nn++)
#pragma unroll
            for (int q = 0; q < 4; q++) sacc[nn][q] = 0.f;

#pragma unroll
        for (int ks = 0; ks < 16; ks++) {
            uint32_t kb[4][4];
#pragma unroll
            for (int np = 0; np < 4; np++)
                ldsm4(kb[np], sK + (uint32_t)(np * 16 * AQ_STR) * 4 + ks * 32 + lmQ);
#pragma unroll
            for (int np = 0; np < 4; np++) {
                mma_tf32(sacc[2 * np],     qf[ks], kb[np][0], kb[np][2]);
                mma_tf32(sacc[2 * np + 1], qf[ks], kb[np][1], kb[np][3]);
            }
        }

        // ---- online softmax (rows live in lane quads) ----
        float mx0 = -1e30f, mx1 = -1e30f;
#pragma unroll
        for (int nn = 0; nn < 8; nn++) {
            mx0 = fmaxf(mx0, fmaxf(sacc[nn][0], sacc[nn][1]));
            mx1 = fmaxf(mx1, fmaxf(sacc[nn][2], sacc[nn][3]));
        }
        mx0 = fmaxf(mx0, __shfl_xor_sync(~0u, mx0, 1));
        mx0 = fmaxf(mx0, __shfl_xor_sync(~0u, mx0, 2));
        mx1 = fmaxf(mx1, __shfl_xor_sync(~0u, mx1, 1));
        mx1 = fmaxf(mx1, __shfl_xor_sync(~0u, mx1, 2));

        float nm0 = fmaxf(m0, mx0), nm1 = fmaxf(m1, mx1);
        float a0 = __expf(m0 - nm0), a1 = __expf(m1 - nm1);
        m0 = nm0; m1 = nm1;

        float s0 = 0.f, s1 = 0.f;
#pragma unroll
        for (int nn = 0; nn < 8; nn++) {
            sacc[nn][0] = __expf(sacc[nn][0] - nm0); s0 += sacc[nn][0];
            sacc[nn][1] = __expf(sacc[nn][1] - nm0); s0 += sacc[nn][1];
            sacc[nn][2] = __expf(sacc[nn][2] - nm1); s1 += sacc[nn][2];
            sacc[nn][3] = __expf(sacc[nn][3] - nm1); s1 += sacc[nn][3];
        }
        s0 += __shfl_xor_sync(~0u, s0, 1); s0 += __shfl_xor_sync(~0u, s0, 2);
        s1 += __shfl_xor_sync(~0u, s1, 1); s1 += __shfl_xor_sync(~0u, s1, 2);
        l0 = l0 * a0 + s0; l1 = l1 * a1 + s1;

#pragma unroll
        for (int nt = 0; nt < 16; nt++) {
            of[nt][0] *= a0; of[nt][1] *= a0;
            of[nt][2] *= a1; of[nt][3] *= a1;
        }

        // ---- store P (tf32) into Ps (overlaps dead Q region) ----
        {
            float* Ps = sm;
            int r0 = w * 16 + qr;
#pragma unroll
            for (int nn = 0; nn < 8; nn++) {
                int col = nn * 8 + c4 * 2;
                uint32_t p0 = f2tf(sacc[nn][0]), p1 = f2tf(sacc[nn][1]);
                *reinterpret_cast<uint2*>(&Ps[r0 * AP_STR + col]) = make_uint2(p0, p1);
                uint32_t p2 = f2tf(sacc[nn][2]), p3 = f2tf(sacc[nn][3]);
                *reinterpret_cast<uint2*>(&Ps[(r0 + 8) * AP_STR + col]) = make_uint2(p2, p3);
            }
        }
        __syncthreads();

        // ---- O += P V ----
        {
            uint32_t pbase = sQ + (uint32_t)(w * 16 * AP_STR) * 4;
#pragma unroll
            for (int ks = 0; ks < 8; ks++) {
                uint32_t pf[4];
                ldsm4(pf, pbase + ks * 32 + lmP);
#pragma unroll
                for (int nt = 0; nt < 16; nt++) {
                    uint32_t b0 = __float_as_uint(Vs[(ks * 8 + c4) * AQ_STR + nt * 8 + qr]);
                    uint32_t b1 = __float_as_uint(Vs[(ks * 8 + 4 + c4) * AQ_STR + nt * 8 + qr]);
                    mma_tf32(of[nt], pf, b0, b1);
                }
            }
        }
        __syncthreads();
    }

    // ---- epilogue: O / l -> g_o[(b*L + q)*DIM + h*128 + d] ----
    {
        float inv0 = 1.0f / l0, inv1 = 1.0f / l1;
        int r0 = q0 + w * 16 + qr;
        float* og0 = g_o + ((size_t)(b * L_) + r0) * DIM_ + h * HD_;
        float* og1 = og0 + (size_t)8 * DIM_;
#pragma unroll
        for (int nt = 0; nt < 16; nt++) {
            int d = nt * 8 + c4 * 2;
            *reinterpret_cast<float2*>(&og0[d]) =
                make_float2(of[nt][0] * inv0, of[nt][1] * inv0);
            *reinterpret_cast<float2*>(&og1[d]) =
                make_float2(of[nt][2] * inv1, of[nt][3] * inv1);
        }
    }
}

// ============================================================================
extern "C" void kernel_launch(void* const* d_in, const int* in_sizes, int n_in,
                              void* d_out, int out_size)
{
    const float* x       = (const float*)d_in[0];
    const float* pe      = (const float*)d_in[1];
    const float* Wqkv    = (const float*)d_in[2];
    const float* bqkv    = (const float*)d_in[3];
    const float* q_scale = (const float*)d_in[4];
    const float* k_scale = (const float*)d_in[5];
    const float* Wproj   = (const float*)d_in[6];
    const float* bproj   = (const float*)d_in[7];
    float* out = (float*)d_out;

    cudaFuncSetAttribute(gemm_mma<1>, cudaFuncAttributeMaxDynamicSharedMemorySize, GEMM_SMEM);
    cudaFuncSetAttribute(gemm_mma<0>, cudaFuncAttributeMaxDynamicSharedMemorySize, GEMM_SMEM);
    cudaFuncSetAttribute(attn_mma, cudaFuncAttributeMaxDynamicSharedMemorySize, ATTN_SMEM);

    // 1) QKV GEMM (tf32 mma.sync + ldmatrix) + scatter
    {
        dim3 grid(N_QKV / 128, TOK / 256);
        gemm_mma<1><<<grid, 256, GEMM_SMEM>>>(x, Wqkv, bqkv, nullptr, TOK, N_QKV, DIM_);
    }
    // 2) RMSNorm + RoPE
    {
        int rows = 2 * B_ * H_ * L_;
        rmsrope_kernel<<<rows / 8, 256>>>(pe, q_scale, k_scale);
    }
    // 3) flash attention (tf32 mma.sync)
    {
        dim3 grid(L_ / 128, H_, B_);
        attn_mma<<<grid, 256, ATTN_SMEM>>>();
    }
    // 4) output projection (tf32 mma.sync + ldmatrix)
    {
        dim3 grid(DIM_ / 128, TOK / 256);
        gemm_mma<0><<<grid, 256, GEMM_SMEM>>>(nullptr, Wproj, bproj, out, TOK, DIM_, DIM_);
    }
}

// round 11
// speedup vs baseline: 3.3960x; 1.0068x over previous
#include <cuda_runtime.h>
#include <cstdint>

#define B_   2
#define L_   2048
#define DIM_ 3072
#define H_   24
#define HD_  128
#define TOK  (B_ * L_)          // 4096
#define N_QKV (3 * DIM_)        // 9216

// ---------------- scratch (device globals — no allocation allowed) ----------
__device__ float g_q[(size_t)B_ * H_ * L_ * HD_];
__device__ float g_k[(size_t)B_ * H_ * L_ * HD_];
__device__ float g_v[(size_t)B_ * H_ * L_ * HD_];
__device__ float g_o[(size_t)TOK * DIM_];

// ============================================================================
// helpers
// ============================================================================
__device__ __forceinline__ uint32_t f2tf(float f) {
    uint32_t r; asm("cvt.rna.tf32.f32 %0, %1;" : "=r"(r) : "f"(f)); return r;
}
__device__ __forceinline__ void mma_tf32(float* d, const uint32_t* a,
                                         uint32_t b0, uint32_t b1) {
    asm volatile(
        "mma.sync.aligned.m16n8k8.row.col.f32.tf32.tf32.f32 "
        "{%0,%1,%2,%3}, {%4,%5,%6,%7}, {%8,%9}, {%0,%1,%2,%3};"
        : "+f"(d[0]), "+f"(d[1]), "+f"(d[2]), "+f"(d[3])
        : "r"(a[0]), "r"(a[1]), "r"(a[2]), "r"(a[3]), "r"(b0), "r"(b1));
}
__device__ __forceinline__ uint32_t smem_u32(const void* p) {
    uint32_t a;
    asm("{ .reg .u64 t; cvta.to.shared.u64 t, %1; cvt.u32.u64 %0, t; }"
        : "=r"(a) : "l"(p));
    return a;
}
// ldmatrix x4 (b32 view): lane addr row = base+(l&8)+(l&7), col = k0+(l>>4)*4
// d0=M[qr][c4] d1=M[qr+8][c4] d2=M[qr][c4+4] d3=M[qr+8][c4+4]
__device__ __forceinline__ void ldsm4(uint32_t* d, uint32_t saddr) {
    asm volatile("ldmatrix.sync.aligned.m8n8.x4.shared.b16 {%0,%1,%2,%3}, [%4];"
        : "=r"(d[0]), "=r"(d[1]), "=r"(d[2]), "=r"(d[3]) : "r"(saddr));
}

// ============================================================================
// tf32 mma.sync GEMM, 2 CTAs/SM.
// C[M,N] = A[M,K] @ W[N,K]^T + bias[N]
// BM=128, BN=128, BK=16. 256 threads = 8 warps (2m x 4n), warp tile 64x32.
// SMEM rows stride 20 floats (80B) -> ldmatrix conflict-free. 40KB/CTA.
// MODE 0: A = g_o, C -> Cout row-major. MODE 1: scatter into g_q/g_k/g_v.
// ============================================================================
#define ASTRIDE 20
#define T_FLOATS (128 * ASTRIDE)                    // one matrix, one stage
#define GEMM_SMEM (4 * T_FLOATS * 4)                // 2 stages x (A+B) = 40960 B

template <int MODE>
__global__ __launch_bounds__(256, 2) void gemm_mma(
    const float* __restrict__ A_in, const float* __restrict__ W,
    const float* __restrict__ bias, float* __restrict__ Cout,
    int M, int N, int K)
{
    extern __shared__ float dsm[];
    // layout: [stage0 A][stage0 B][stage1 A][stage1 B]
    const float* A = (MODE == 0) ? g_o : A_in;

    const int tid = threadIdx.x;
    const int wid = tid >> 5, lane = tid & 31;
    const int wm = wid >> 2, wn = wid & 3;          // 2 x 4 warp grid
    const int qr = lane >> 2, c4 = lane & 3;
    const int row0 = blockIdx.y * 128;
    const int col0 = blockIdx.x * 128;
    const int NSTEP = K / 16;

    const int lrow = tid >> 2;       // 0..63
    const int lc4  = (tid & 3) * 4;  // 0,4,8,12

    const int lmr = (lane & 7) + (lane & 8);
    const int lmc = (lane >> 4) << 2;
    const uint32_t lmoff = (uint32_t)(lmr * ASTRIDE + lmc) * 4;
    const uint32_t sBase = smem_u32(dsm);

    float acc[4][4][4];
#pragma unroll
    for (int mm = 0; mm < 4; mm++)
#pragma unroll
        for (int nn = 0; nn < 4; nn++)
#pragma unroll
            for (int q = 0; q < 4; q++) acc[mm][nn][q] = 0.f;

    // ---- prologue: stage 0 ----
#pragma unroll
    for (int p = 0; p < 2; p++) {
        int r = lrow + 64 * p;
        float4 v = *reinterpret_cast<const float4*>(&A[(size_t)(row0 + r) * K + lc4]);
        *reinterpret_cast<float4*>(&dsm[r * ASTRIDE + lc4]) =
            make_float4(__uint_as_float(f2tf(v.x)), __uint_as_float(f2tf(v.y)),
                        __uint_as_float(f2tf(v.z)), __uint_as_float(f2tf(v.w)));
        float4 w = *reinterpret_cast<const float4*>(&W[(size_t)(col0 + r) * K + lc4]);
        *reinterpret_cast<float4*>(&dsm[T_FLOATS + r * ASTRIDE + lc4]) =
            make_float4(__uint_as_float(f2tf(w.x)), __uint_as_float(f2tf(w.y)),
                        __uint_as_float(f2tf(w.z)), __uint_as_float(f2tf(w.w)));
    }
    __syncthreads();

    int buf = 0;
    for (int step = 0; step < NSTEP; ++step) {
        const bool more = (step + 1) < NSTEP;
        const int kt = (step + 1) * 16;

        float4 pa[2], pb[2];
        if (more) {
#pragma unroll
            for (int p = 0; p < 2; p++) {
                int r = lrow + 64 * p;
                pa[p] = *reinterpret_cast<const float4*>(
                    &A[(size_t)(row0 + r) * K + kt + lc4]);
                pb[p] = *reinterpret_cast<const float4*>(
                    &W[(size_t)(col0 + r) * K + kt + lc4]);
            }
        }

        // ---- compute on current buffer ----
        {
            const uint32_t sAb = sBase + (uint32_t)(buf * 2 * T_FLOATS) * 4;
            const uint32_t sBb = sAb + (uint32_t)T_FLOATS * 4;
#pragma unroll
            for (int ks = 0; ks < 2; ks++) {
                uint32_t a[4][4], bb[2][4];
#pragma unroll
                for (int mm = 0; mm < 4; mm++)
                    ldsm4(a[mm], sAb + (uint32_t)((wm * 64 + mm * 16) * ASTRIDE * 4)
                                   + ks * 32 + lmoff);
#pragma unroll
                for (int np = 0; np < 2; np++)
                    ldsm4(bb[np], sBb + (uint32_t)((wn * 32 + np * 16) * ASTRIDE * 4)
                                    + ks * 32 + lmoff);
#pragma unroll
                for (int np = 0; np < 2; np++)
#pragma unroll
                    for (int mm = 0; mm < 4; mm++) {
                        mma_tf32(acc[mm][2 * np],     a[mm], bb[np][0], bb[np][2]);
                        mma_tf32(acc[mm][2 * np + 1], a[mm], bb[np][1], bb[np][3]);
                    }
            }
        }

        // ---- store next tile ----
        if (more) {
            int nbuf = buf ^ 1;
            float* Ab = dsm + nbuf * 2 * T_FLOATS;
            float* Bb = Ab + T_FLOATS;
#pragma unroll
            for (int p = 0; p < 2; p++) {
                int r = lrow + 64 * p;
                float4 v = pa[p];
                *reinterpret_cast<float4*>(&Ab[r * ASTRIDE + lc4]) =
                    make_float4(__uint_as_float(f2tf(v.x)), __uint_as_float(f2tf(v.y)),
                                __uint_as_float(f2tf(v.z)), __uint_as_float(f2tf(v.w)));
                float4 w = pb[p];
                *reinterpret_cast<float4*>(&Bb[r * ASTRIDE + lc4]) =
                    make_float4(__uint_as_float(f2tf(w.x)), __uint_as_float(f2tf(w.y)),
                                __uint_as_float(f2tf(w.z)), __uint_as_float(f2tf(w.w)));
            }
            __syncthreads();
            buf = nbuf;
        }
    }

    // ---- epilogue ----
#pragma unroll
    for (int nn = 0; nn < 4; nn++) {
        const int n = col0 + wn * 32 + nn * 8 + c4 * 2;
        const float b0 = bias[n], b1 = bias[n + 1];
#pragma unroll
        for (int mm = 0; mm < 4; mm++) {
            const int mrow = row0 + wm * 64 + mm * 16 + qr;
#pragma unroll
            for (int half = 0; half < 2; half++) {
                const int m = mrow + half * 8;
                float2 v = make_float2(acc[mm][nn][half * 2] + b0,
                                       acc[mm][nn][half * 2 + 1] + b1);
                if (MODE == 0) {
                    *reinterpret_cast<float2*>(&Cout[(size_t)m * N + n]) = v;
                } else {
                    int s   = n / DIM_;
                    int rem = n - s * DIM_;
                    int h   = rem >> 7;
                    int d   = rem & 127;
                    int b   = m >> 11;
                    int l   = m & 2047;
                    float* base = (s == 0) ? g_q : (s == 1) ? g_k : g_v;
                    *reinterpret_cast<float2*>(
                        &base[((size_t)(b * H_ + h) * L_ + l) * HD_ + d]) = v;
                }
            }
        }
    }
}

// ============================================================================
// RMSNorm + RoPE (unchanged)
// ============================================================================
__global__ __launch_bounds__(256) void rmsrope_kernel(
    const float* __restrict__ pe,
    const float* __restrict__ q_scale,
    const float* __restrict__ k_scale)
{
    int gw   = (blockIdx.x * blockDim.x + threadIdx.x) >> 5;
    int lane = threadIdx.x & 31;
    const int total = B_ * H_ * L_;
    bool is_k = gw >= total;
    int row = is_k ? gw - total : gw;
    float* ptr = (is_k ? g_k : g_q) + (size_t)row * HD_;
    const float* scale = is_k ? k_scale : q_scale;
    int l = row & (L_ - 1);

    float4 v = *reinterpret_cast<float4*>(&ptr[lane * 4]);
    float ss = v.x * v.x + v.y * v.y + v.z * v.z + v.w * v.w;
#pragma unroll
    for (int o = 16; o; o >>= 1) ss += __shfl_xor_sync(~0u, ss, o);
    float rrms = rsqrtf(ss * (1.0f / 128.0f) + 1e-6f);

    float4 sc = *reinterpret_cast<const float4*>(&scale[lane * 4]);
    v.x *= rrms * sc.x; v.y *= rrms * sc.y;
    v.z *= rrms * sc.z; v.w *= rrms * sc.w;

    const float* pe_l = pe + (size_t)l * 256;
    int i0 = lane * 2;
    float4 m0 = *reinterpret_cast<const float4*>(&pe_l[i0 * 4]);
    float o0 = m0.x * v.x + m0.y * v.y;
    float o1 = m0.z * v.x + m0.w * v.y;
    int i1 = i0 + 1;
    float4 m1 = *reinterpret_cast<const float4*>(&pe_l[i1 * 4]);
    float o2 = m1.x * v.z + m1.y * v.w;
    float o3 = m1.z * v.z + m1.w * v.w;

    *reinterpret_cast<float4*>(&ptr[lane * 4]) = make_float4(o0, o1, o2, o3);
}

// ============================================================================
// Flash attention, tf32 mma.sync (unchanged from round 10)
// ============================================================================
#define AQ_STR 132
#define AP_STR 68
#define ATTN_SMEM ((128 * AQ_STR + 2 * 64 * AQ_STR) * 4)

__global__ __launch_bounds__(256, 1) void attn_mma()
{
    extern __shared__ float sm[];
    float* Qs = sm;                        // 128 x 132 (later reused as Ps 128 x 68)
    float* Ks = sm + 128 * AQ_STR;         // 64 x 132
    float* Vs = Ks + 64 * AQ_STR;          // 64 x 132

    const int tid = threadIdx.x, w = tid >> 5, lane = tid & 31;
    const int qr = lane >> 2, c4 = lane & 3;
    const int q0 = blockIdx.x * 128;
    const int h = blockIdx.y, b = blockIdx.z;

    const size_t hoff = (size_t)(b * H_ + h) * L_ * HD_;
    const float* qg = g_q + hoff;
    const float* kg = g_k + hoff;
    const float* vg = g_v + hoff;

    const float scl = 0.08838834764831845f;   // 1/sqrt(128), folded into Q

    const int lmr = (lane & 7) + (lane & 8);
    const int lmc = (lane >> 4) << 2;
    const uint32_t lmQ = (uint32_t)(lmr * AQ_STR + lmc) * 4;
    const uint32_t lmP = (uint32_t)(lmr * AP_STR + lmc) * 4;
    const uint32_t sQ = smem_u32(sm);
    const uint32_t sK = smem_u32(Ks);

    // ---- load Q (scaled, tf32) ----
#pragma unroll
    for (int p = 0; p < 16; p++) {
        int fi = tid + 256 * p;
        int r = fi >> 5, d4 = (fi & 31) * 4;
        float4 v = *reinterpret_cast<const float4*>(&qg[(size_t)(q0 + r) * HD_ + d4]);
        *reinterpret_cast<float4*>(&Qs[r * AQ_STR + d4]) =
            make_float4(__uint_as_float(f2tf(v.x * scl)),
                        __uint_as_float(f2tf(v.y * scl)),
                        __uint_as_float(f2tf(v.z * scl)),
                        __uint_as_float(f2tf(v.w * scl)));
    }
    __syncthreads();

    uint32_t qf[16][4];
    {
        uint32_t qbase = sQ + (uint32_t)(w * 16 * AQ_STR) * 4;
#pragma unroll
        for (int ks = 0; ks < 16; ks++)
            ldsm4(qf[ks], qbase + ks * 32 + lmQ);
    }

    float of[16][4];
#pragma unroll
    for (int nt = 0; nt < 16; nt++)
#pragma unroll
        for (int q = 0; q < 4; q++) of[nt][q] = 0.f;
    float m0 = -1e30f, m1 = -1e30f, l0 = 0.f, l1 = 0.f;

    for (int kt = 0; kt < L_; kt += 64) {
#pragma unroll
        for (int p = 0; p < 8; p++) {
            int fi = tid + 256 * p;
            int r = fi >> 5, d4 = (fi & 31) * 4;
            float4 kv = *reinterpret_cast<const float4*>(&kg[(size_t)(kt + r) * HD_ + d4]);
            *reinterpret_cast<float4*>(&Ks[r * AQ_STR + d4]) =
                make_float4(__uint_as_float(f2tf(kv.x)), __uint_as_float(f2tf(kv.y)),
                            __uint_as_float(f2tf(kv.z)), __uint_as_float(f2tf(kv.w)));
            float4 vv = *reinterpret_cast<const float4*>(&vg[(size_t)(kt + r) * HD_ + d4]);
            *reinterpret_cast<float4*>(&Vs[r * AQ_STR + d4]) =
                make_float4(__uint_as_float(f2tf(vv.x)), __uint_as_float(f2tf(vv.y)),
                            __uint_as_float(f2tf(vv.z)), __uint_as_float(f2tf(vv.w)));
        }
        __syncthreads();

        float sacc[8][4];
#pragma unroll
        for (int nn = 0; nn < 8; nn++)
#pragma unroll
            for (int q = 0; q < 4; q++) sacc[nn][q] = 0.f;

#pragma unroll
        for (int ks = 0; ks < 16; ks++) {
            uint32_t kb[4][4];
#pragma unroll
            for (int np = 0; np < 4; np++)
                ldsm4(kb[np], sK + (uint32_t)(np * 16 * AQ_STR) * 4 + ks * 32 + lmQ);
#pragma unroll
            for (int np = 0; np < 4; np++) {
                mma_tf32(sacc[2 * np],     qf[ks], kb[np][0], kb[np][2]);
                mma_tf32(sacc[2 * np + 1], qf[ks], kb[np][1], kb[np][3]);
            }
        }

        float mx0 = -1e30f, mx1 = -1e30f;
#pragma unroll
        for (int nn = 0; nn < 8; nn++) {
            mx0 = fmaxf(mx0, fmaxf(sacc[nn][0], sacc[nn][1]));
            mx1 = fmaxf(mx1, fmaxf(sacc[nn][2], sacc[nn][3]));
        }
        mx0 = fmaxf(mx0, __shfl_xor_sync(~0u, mx0, 1));
        mx0 = fmaxf(mx0, __shfl_xor_sync(~0u, mx0, 2));
        mx1 = fmaxf(mx1, __shfl_xor_sync(~0u, mx1, 1));
        mx1 = fmaxf(mx1, __shfl_xor_sync(~0u, mx1, 2));

        float nm0 = fmaxf(m0, mx0), nm1 = fmaxf(m1, mx1);
        float a0 = __expf(m0 - nm0), a1 = __expf(m1 - nm1);
        m0 = nm0; m1 = nm1;

        float s0 = 0.f, s1 = 0.f;
#pragma unroll
        for (int nn = 0; nn < 8; nn++) {
            sacc[nn][0] = __expf(sacc[nn][0] - nm0); s0 += sacc[nn][0];
            sacc[nn][1] = __expf(sacc[nn][1] - nm0); s0 += sacc[nn][1];
            sacc[nn][2] = __expf(sacc[nn][2] - nm1); s1 += sacc[nn][2];
            sacc[nn][3] = __expf(sacc[nn][3] - nm1); s1 += sacc[nn][3];
        }
        s0 += __shfl_xor_sync(~0u, s0, 1); s0 += __shfl_xor_sync(~0u, s0, 2);
        s1 += __shfl_xor_sync(~0u, s1, 1); s1 += __shfl_xor_sync(~0u, s1, 2);
        l0 = l0 * a0 + s0; l1 = l1 * a1 + s1;

#pragma unroll
        for (int nt = 0; nt < 16; nt++) {
            of[nt][0] *= a0; of[nt][1] *= a0;
            of[nt][2] *= a1; of[nt][3] *= a1;
        }

        {
            float* Ps = sm;
            int r0 = w * 16 + qr;
#pragma unroll
            for (int nn = 0; nn < 8; nn++) {
                int col = nn * 8 + c4 * 2;
                uint32_t p0 = f2tf(sacc[nn][0]), p1 = f2tf(sacc[nn][1]);
                *reinterpret_cast<uint2*>(&Ps[r0 * AP_STR + col]) = make_uint2(p0, p1);
                uint32_t p2 = f2tf(sacc[nn][2]), p3 = f2tf(sacc[nn][3]);
                *reinterpret_cast<uint2*>(&Ps[(r0 + 8) * AP_STR + col]) = make_uint2(p2, p3);
            }
        }
        __syncthreads();

        {
            uint32_t pbase = sQ + (uint32_t)(w * 16 * AP_STR) * 4;
#pragma unroll
            for (int ks = 0; ks < 8; ks++) {
                uint32_t pf[4];
                ldsm4(pf, pbase + ks * 32 + lmP);
#pragma unroll
                for (int nt = 0; nt < 16; nt++) {
                    uint32_t b0 = __float_as_uint(Vs[(ks * 8 + c4) * AQ_STR + nt * 8 + qr]);
                    uint32_t b1 = __float_as_uint(Vs[(ks * 8 + 4 + c4) * AQ_STR + nt * 8 + qr]);
                    mma_tf32(of[nt], pf, b0, b1);
                }
            }
        }
        __syncthreads();
    }

    {
        float inv0 = 1.0f / l0, inv1 = 1.0f / l1;
        int r0 = q0 + w * 16 + qr;
        float* og0 = g_o + ((size_t)(b * L_) + r0) * DIM_ + h * HD_;
        float* og1 = og0 + (size_t)8 * DIM_;
#pragma unroll
        for (int nt = 0; nt < 16; nt++) {
            int d = nt * 8 + c4 * 2;
            *reinterpret_cast<float2*>(&og0[d]) =
                make_float2(of[nt][0] * inv0, of[nt][1] * inv0);
            *reinterpret_cast<float2*>(&og1[d]) =
                make_float2(of[nt][2] * inv1, of[nt][3] * inv1);
        }
    }
}

// ============================================================================
extern "C" void kernel_launch(void* const* d_in, const int* in_sizes, int n_in,
                              void* d_out, int out_size)
{
    const float* x       = (const float*)d_in[0];
    const float* pe      = (const float*)d_in[1];
    const float* Wqkv    = (const float*)d_in[2];
    const float* bqkv    = (const float*)d_in[3];
    const float* q_scale = (const float*)d_in[4];
    const float* k_scale = (const float*)d_in[5];
    const float* Wproj   = (const float*)d_in[6];
    const float* bproj   = (const float*)d_in[7];
    float* out = (float*)d_out;

    cudaFuncSetAttribute(gemm_mma<1>, cudaFuncAttributeMaxDynamicSharedMemorySize, GEMM_SMEM);
    cudaFuncSetAttribute(gemm_mma<0>, cudaFuncAttributeMaxDynamicSharedMemorySize, GEMM_SMEM);
    cudaFuncSetAttribute(attn_mma, cudaFuncAttributeMaxDynamicSharedMemorySize, ATTN_SMEM);

    // 1) QKV GEMM (tf32 mma.sync + ldmatrix, 2 CTA/SM) + scatter
    {
        dim3 grid(N_QKV / 128, TOK / 128);
        gemm_mma<1><<<grid, 256, GEMM_SMEM>>>(x, Wqkv, bqkv, nullptr, TOK, N_QKV, DIM_);
    }
    // 2) RMSNorm + RoPE
    {
        int rows = 2 * B_ * H_ * L_;
        rmsrope_kernel<<<rows / 8, 256>>>(pe, q_scale, k_scale);
    }
    // 3) flash attention (tf32 mma.sync)
    {
        dim3 grid(L_ / 128, H_, B_);
        attn_mma<<<grid, 256, ATTN_SMEM>>>();
    }
    // 4) output projection (tf32 mma.sync + ldmatrix, 2 CTA/SM)
    {
        dim3 grid(DIM_ / 128, TOK / 128);
        gemm_mma<0><<<grid, 256, GEMM_SMEM>>>(nullptr, Wproj, bproj, out, TOK, DIM_, DIM_);
    }
}

// round 12
// speedup vs baseline: 3.5010x; 1.0309x over previous
#include <cuda_runtime.h>
#include <cstdint>

#define B_   2
#define L_   2048
#define DIM_ 3072
#define H_   24
#define HD_  128
#define TOK  (B_ * L_)          // 4096
#define N_QKV (3 * DIM_)        // 9216

// ---------------- scratch (device globals — no allocation allowed) ----------
__device__ float g_q[(size_t)B_ * H_ * L_ * HD_];
__device__ float g_k[(size_t)B_ * H_ * L_ * HD_];
__device__ float g_v[(size_t)B_ * H_ * L_ * HD_];
__device__ float g_o[(size_t)TOK * DIM_];
// tf32-pre-rounded copies of inputs
__device__ float g_xr[(size_t)TOK * DIM_];
__device__ float g_wq[(size_t)N_QKV * DIM_];
__device__ float g_wp[(size_t)DIM_ * DIM_];

// ============================================================================
// helpers
// ============================================================================
__device__ __forceinline__ uint32_t f2tf(float f) {
    uint32_t r; asm("cvt.rna.tf32.f32 %0, %1;" : "=r"(r) : "f"(f)); return r;
}
__device__ __forceinline__ void mma_tf32(float* d, const uint32_t* a,
                                         uint32_t b0, uint32_t b1) {
    asm volatile(
        "mma.sync.aligned.m16n8k8.row.col.f32.tf32.tf32.f32 "
        "{%0,%1,%2,%3}, {%4,%5,%6,%7}, {%8,%9}, {%0,%1,%2,%3};"
        : "+f"(d[0]), "+f"(d[1]), "+f"(d[2]), "+f"(d[3])
        : "r"(a[0]), "r"(a[1]), "r"(a[2]), "r"(a[3]), "r"(b0), "r"(b1));
}
__device__ __forceinline__ uint32_t smem_u32(const void* p) {
    uint32_t a;
    asm("{ .reg .u64 t; cvta.to.shared.u64 t, %1; cvt.u32.u64 %0, t; }"
        : "=r"(a) : "l"(p));
    return a;
}
__device__ __forceinline__ void ldsm4(uint32_t* d, uint32_t saddr) {
    asm volatile("ldmatrix.sync.aligned.m8n8.x4.shared.b16 {%0,%1,%2,%3}, [%4];"
        : "=r"(d[0]), "=r"(d[1]), "=r"(d[2]), "=r"(d[3]) : "r"(saddr));
}
__device__ __forceinline__ void cpa16(uint32_t s, const float* g) {
    asm volatile("cp.async.cg.shared.global [%0], [%1], 16;"
                 :: "r"(s), "l"(g) : "memory");
}
#define CP_COMMIT() asm volatile("cp.async.commit_group;" ::: "memory")
#define CP_WAIT2()  asm volatile("cp.async.wait_group 2;" ::: "memory")

// ============================================================================
// pre-round inputs to tf32 (RNA) — bit-identical to converting at STS time
// ============================================================================
__global__ __launch_bounds__(256) void round_tf32(
    const float4* __restrict__ in, float4* __restrict__ out, int n4)
{
    int i = blockIdx.x * 256 + threadIdx.x;
    if (i < n4) {
        float4 v = in[i];
        out[i] = make_float4(__uint_as_float(f2tf(v.x)), __uint_as_float(f2tf(v.y)),
                             __uint_as_float(f2tf(v.z)), __uint_as_float(f2tf(v.w)));
    }
}

// ============================================================================
// tf32 mma.sync GEMM, cp.async 4-stage pipeline, 2 CTAs/SM.
// C[M,N] = A[M,K] @ W[N,K]^T + bias[N]; A and W are pre-rounded tf32 values.
// BM=128, BN=128, BK=16. 256 threads = 8 warps (2m x 4n), warp tile 64x32.
// SMEM rows stride 20 floats (80B): 16B-aligned cp.async dsts, ldmatrix
// conflict-free. 80KB/CTA (4 stages x 20KB).
// MODE 0: C -> Cout row-major. MODE 1: scatter into g_q/g_k/g_v.
// ============================================================================
#define ASTRIDE 20
#define T_FLOATS (128 * ASTRIDE)            // 2560 floats: one matrix, one stage
#define STG_BYTES (2 * T_FLOATS * 4)        // 20480 B: A+B, one stage
#define GEMM_SMEM (4 * STG_BYTES)           // 81920 B

template <int MODE>
__global__ __launch_bounds__(256, 2) void gemm_mma(
    const float* __restrict__ A, const float* __restrict__ W,
    const float* __restrict__ bias, float* __restrict__ Cout,
    int M, int N, int K)
{
    extern __shared__ float dsm[];

    const int tid = threadIdx.x;
    const int wid = tid >> 5, lane = tid & 31;
    const int wm = wid >> 2, wn = wid & 3;          // 2 x 4 warp grid
    const int qr = lane >> 2, c4 = lane & 3;
    const int row0 = blockIdx.y * 128;
    const int col0 = blockIdx.x * 128;
    const int NSTEP = K / 16;

    const int lrow = tid >> 2;       // 0..63
    const int lc4  = (tid & 3) * 4;  // 0,4,8,12

    const int lmr = (lane & 7) + (lane & 8);
    const int lmc = (lane >> 4) << 2;
    const uint32_t lmoff = (uint32_t)(lmr * ASTRIDE + lmc) * 4;
    const uint32_t sBase = smem_u32(dsm);

    // per-thread copy sources / dest offsets
    const float* ga = A + (size_t)(row0 + lrow) * K + lc4;
    const float* gb = W + (size_t)(col0 + lrow) * K + lc4;
    const uint32_t dOff = (uint32_t)(lrow * ASTRIDE + lc4) * 4;
    const uint32_t dRow64 = (uint32_t)(64 * ASTRIDE) * 4;

    float acc[4][4][4];
#pragma unroll
    for (int mm = 0; mm < 4; mm++)
#pragma unroll
        for (int nn = 0; nn < 4; nn++)
#pragma unroll
            for (int q = 0; q < 4; q++) acc[mm][nn][q] = 0.f;

    // ---- prologue: stages 0..2 ----
#pragma unroll
    for (int st = 0; st < 3; st++) {
        uint32_t s0 = sBase + st * STG_BYTES + dOff;
        int kt = st * 16;
        cpa16(s0, ga + kt);
        cpa16(s0 + dRow64, ga + (size_t)64 * K + kt);
        uint32_t s1 = s0 + T_FLOATS * 4;
        cpa16(s1, gb + kt);
        cpa16(s1 + dRow64, gb + (size_t)64 * K + kt);
        CP_COMMIT();
    }

    for (int s = 0; s < NSTEP; ++s) {
        CP_WAIT2();                 // stage s resident
        __syncthreads();            // all warps done with compute(s-1)

        // issue stage s+3 (overwrites buffer consumed at s-1)
        if (s + 3 < NSTEP) {
            int st = (s + 3) & 3, kt = (s + 3) * 16;
            uint32_t s0 = sBase + st * STG_BYTES + dOff;
            cpa16(s0, ga + kt);
            cpa16(s0 + dRow64, ga + (size_t)64 * K + kt);
            uint32_t s1 = s0 + T_FLOATS * 4;
            cpa16(s1, gb + kt);
            cpa16(s1 + dRow64, gb + (size_t)64 * K + kt);
        }
        CP_COMMIT();

        // ---- compute stage s ----
        const uint32_t sAb = sBase + (uint32_t)((s & 3) * STG_BYTES);
        const uint32_t sBb = sAb + T_FLOATS * 4;
#pragma unroll
        for (int ks = 0; ks < 2; ks++) {
            uint32_t a[4][4], bb[2][4];
#pragma unroll
            for (int mm = 0; mm < 4; mm++)
                ldsm4(a[mm], sAb + (uint32_t)((wm * 64 + mm * 16) * ASTRIDE * 4)
                               + ks * 32 + lmoff);
#pragma unroll
            for (int np = 0; np < 2; np++)
                ldsm4(bb[np], sBb + (uint32_t)((wn * 32 + np * 16) * ASTRIDE * 4)
                                + ks * 32 + lmoff);
#pragma unroll
            for (int np = 0; np < 2; np++)
#pragma unroll
                for (int mm = 0; mm < 4; mm++) {
                    mma_tf32(acc[mm][2 * np],     a[mm], bb[np][0], bb[np][2]);
                    mma_tf32(acc[mm][2 * np + 1], a[mm], bb[np][1], bb[np][3]);
                }
        }
    }

    // ---- epilogue ----
#pragma unroll
    for (int nn = 0; nn < 4; nn++) {
        const int n = col0 + wn * 32 + nn * 8 + c4 * 2;
        const float b0 = bias[n], b1 = bias[n + 1];
#pragma unroll
        for (int mm = 0; mm < 4; mm++) {
            const int mrow = row0 + wm * 64 + mm * 16 + qr;
#pragma unroll
            for (int half = 0; half < 2; half++) {
                const int m = mrow + half * 8;
                float2 v = make_float2(acc[mm][nn][half * 2] + b0,
                                       acc[mm][nn][half * 2 + 1] + b1);
                if (MODE == 0) {
                    *reinterpret_cast<float2*>(&Cout[(size_t)m * N + n]) = v;
                } else {
                    int s   = n / DIM_;
                    int rem = n - s * DIM_;
                    int h   = rem >> 7;
                    int d   = rem & 127;
                    int b   = m >> 11;
                    int l   = m & 2047;
                    float* base = (s == 0) ? g_q : (s == 1) ? g_k : g_v;
                    *reinterpret_cast<float2*>(
                        &base[((size_t)(b * H_ + h) * L_ + l) * HD_ + d]) = v;
                }
            }
        }
    }
}

// ============================================================================
// RMSNorm + RoPE (unchanged)
// ============================================================================
__global__ __launch_bounds__(256) void rmsrope_kernel(
    const float* __restrict__ pe,
    const float* __restrict__ q_scale,
    const float* __restrict__ k_scale)
{
    int gw   = (blockIdx.x * blockDim.x + threadIdx.x) >> 5;
    int lane = threadIdx.x & 31;
    const int total = B_ * H_ * L_;
    bool is_k = gw >= total;
    int row = is_k ? gw - total : gw;
    float* ptr = (is_k ? g_k : g_q) + (size_t)row * HD_;
    const float* scale = is_k ? k_scale : q_scale;
    int l = row & (L_ - 1);

    float4 v = *reinterpret_cast<float4*>(&ptr[lane * 4]);
    float ss = v.x * v.x + v.y * v.y + v.z * v.z + v.w * v.w;
#pragma unroll
    for (int o = 16; o; o >>= 1) ss += __shfl_xor_sync(~0u, ss, o);
    float rrms = rsqrtf(ss * (1.0f / 128.0f) + 1e-6f);

    float4 sc = *reinterpret_cast<const float4*>(&scale[lane * 4]);
    v.x *= rrms * sc.x; v.y *= rrms * sc.y;
    v.z *= rrms * sc.z; v.w *= rrms * sc.w;

    const float* pe_l = pe + (size_t)l * 256;
    int i0 = lane * 2;
    float4 m0 = *reinterpret_cast<const float4*>(&pe_l[i0 * 4]);
    float o0 = m0.x * v.x + m0.y * v.y;
    float o1 = m0.z * v.x + m0.w * v.y;
    int i1 = i0 + 1;
    float4 m1 = *reinterpret_cast<const float4*>(&pe_l[i1 * 4]);
    float o2 = m1.x * v.z + m1.y * v.w;
    float o3 = m1.z * v.z + m1.w * v.w;

    *reinterpret_cast<float4*>(&ptr[lane * 4]) = make_float4(o0, o1, o2, o3);
}

// ============================================================================
// Flash attention, tf32 mma.sync (round-10 design; epilogue now writes
// tf32-rounded g_o so the proj GEMM can copy it raw)
// ============================================================================
#define AQ_STR 132
#define AP_STR 68
#define ATTN_SMEM ((128 * AQ_STR + 2 * 64 * AQ_STR) * 4)

__global__ __launch_bounds__(256, 1) void attn_mma()
{
    extern __shared__ float sm[];
    float* Qs = sm;                        // 128 x 132 (later reused as Ps)
    float* Ks = sm + 128 * AQ_STR;         // 64 x 132
    float* Vs = Ks + 64 * AQ_STR;          // 64 x 132

    const int tid = threadIdx.x, w = tid >> 5, lane = tid & 31;
    const int qr = lane >> 2, c4 = lane & 3;
    const int q0 = blockIdx.x * 128;
    const int h = blockIdx.y, b = blockIdx.z;

    const size_t hoff = (size_t)(b * H_ + h) * L_ * HD_;
    const float* qg = g_q + hoff;
    const float* kg = g_k + hoff;
    const float* vg = g_v + hoff;

    const float scl = 0.08838834764831845f;   // 1/sqrt(128), folded into Q

    const int lmr = (lane & 7) + (lane & 8);
    const int lmc = (lane >> 4) << 2;
    const uint32_t lmQ = (uint32_t)(lmr * AQ_STR + lmc) * 4;
    const uint32_t lmP = (uint32_t)(lmr * AP_STR + lmc) * 4;
    const uint32_t sQ = smem_u32(sm);
    const uint32_t sK = smem_u32(Ks);

#pragma unroll
    for (int p = 0; p < 16; p++) {
        int fi = tid + 256 * p;
        int r = fi >> 5, d4 = (fi & 31) * 4;
        float4 v = *reinterpret_cast<const float4*>(&qg[(size_t)(q0 + r) * HD_ + d4]);
        *reinterpret_cast<float4*>(&Qs[r * AQ_STR + d4]) =
            make_float4(__uint_as_float(f2tf(v.x * scl)),
                        __uint_as_float(f2tf(v.y * scl)),
                        __uint_as_float(f2tf(v.z * scl)),
                        __uint_as_float(f2tf(v.w * scl)));
    }
    __syncthreads();

    uint32_t qf[16][4];
    {
        uint32_t qbase = sQ + (uint32_t)(w * 16 * AQ_STR) * 4;
#pragma unroll
        for (int ks = 0; ks < 16; ks++)
            ldsm4(qf[ks], qbase + ks * 32 + lmQ);
    }

    float of[16][4];
#pragma unroll
    for (int nt = 0; nt < 16; nt++)
#pragma unroll
        for (int q = 0; q < 4; q++) of[nt][q] = 0.f;
    float m0 = -1e30f, m1 = -1e30f, l0 = 0.f, l1 = 0.f;

    for (int kt = 0; kt < L_; kt += 64) {
#pragma unroll
        for (int p = 0; p < 8; p++) {
            int fi = tid + 256 * p;
            int r = fi >> 5, d4 = (fi & 31) * 4;
            float4 kv = *reinterpret_cast<const float4*>(&kg[(size_t)(kt + r) * HD_ + d4]);
            *reinterpret_cast<float4*>(&Ks[r * AQ_STR + d4]) =
                make_float4(__uint_as_float(f2tf(kv.x)), __uint_as_float(f2tf(kv.y)),
                            __uint_as_float(f2tf(kv.z)), __uint_as_float(f2tf(kv.w)));
            float4 vv = *reinterpret_cast<const float4*>(&vg[(size_t)(kt + r) * HD_ + d4]);
            *reinterpret_cast<float4*>(&Vs[r * AQ_STR + d4]) =
                make_float4(__uint_as_float(f2tf(vv.x)), __uint_as_float(f2tf(vv.y)),
                            __uint_as_float(f2tf(vv.z)), __uint_as_float(f2tf(vv.w)));
        }
        __syncthreads();

        float sacc[8][4];
#pragma unroll
        for (int nn = 0; nn < 8; nn++)
#pragma unroll
            for (int q = 0; q < 4; q++) sacc[nn][q] = 0.f;

#pragma unroll
        for (int ks = 0; ks < 16; ks++) {
            uint32_t kb[4][4];
#pragma unroll
            for (int np = 0; np < 4; np++)
                ldsm4(kb[np], sK + (uint32_t)(np * 16 * AQ_STR) * 4 + ks * 32 + lmQ);
#pragma unroll
            for (int np = 0; np < 4; np++) {
                mma_tf32(sacc[2 * np],     qf[ks], kb[np][0], kb[np][2]);
                mma_tf32(sacc[2 * np + 1], qf[ks], kb[np][1], kb[np][3]);
            }
        }

        float mx0 = -1e30f, mx1 = -1e30f;
#pragma unroll
        for (int nn = 0; nn < 8; nn++) {
            mx0 = fmaxf(mx0, fmaxf(sacc[nn][0], sacc[nn][1]));
            mx1 = fmaxf(mx1, fmaxf(sacc[nn][2], sacc[nn][3]));
        }
        mx0 = fmaxf(mx0, __shfl_xor_sync(~0u, mx0, 1));
        mx0 = fmaxf(mx0, __shfl_xor_sync(~0u, mx0, 2));
        mx1 = fmaxf(mx1, __shfl_xor_sync(~0u, mx1, 1));
        mx1 = fmaxf(mx1, __shfl_xor_sync(~0u, mx1, 2));

        float nm0 = fmaxf(m0, mx0), nm1 = fmaxf(m1, mx1);
        float a0 = __expf(m0 - nm0), a1 = __expf(m1 - nm1);
        m0 = nm0; m1 = nm1;

        float s0 = 0.f, s1 = 0.f;
#pragma unroll
        for (int nn = 0; nn < 8; nn++) {
            sacc[nn][0] = __expf(sacc[nn][0] - nm0); s0 += sacc[nn][0];
            sacc[nn][1] = __expf(sacc[nn][1] - nm0); s0 += sacc[nn][1];
            sacc[nn][2] = __expf(sacc[nn][2] - nm1); s1 += sacc[nn][2];
            sacc[nn][3] = __expf(sacc[nn][3] - nm1); s1 += sacc[nn][3];
        }
        s0 += __shfl_xor_sync(~0u, s0, 1); s0 += __shfl_xor_sync(~0u, s0, 2);
        s1 += __shfl_xor_sync(~0u, s1, 1); s1 += __shfl_xor_sync(~0u, s1, 2);
        l0 = l0 * a0 + s0; l1 = l1 * a1 + s1;

#pragma unroll
        for (int nt = 0; nt < 16; nt++) {
            of[nt][0] *= a0; of[nt][1] *= a0;
            of[nt][2] *= a1; of[nt][3] *= a1;
        }

        {
            float* Ps = sm;
            int r0 = w * 16 + qr;
#pragma unroll
            for (int nn = 0; nn < 8; nn++) {
                int col = nn * 8 + c4 * 2;
                uint32_t p0 = f2tf(sacc[nn][0]), p1 = f2tf(sacc[nn][1]);
                *reinterpret_cast<uint2*>(&Ps[r0 * AP_STR + col]) = make_uint2(p0, p1);
                uint32_t p2 = f2tf(sacc[nn][2]), p3 = f2tf(sacc[nn][3]);
                *reinterpret_cast<uint2*>(&Ps[(r0 + 8) * AP_STR + col]) = make_uint2(p2, p3);
            }
        }
        __syncthreads();

        {
            uint32_t pbase = sQ + (uint32_t)(w * 16 * AP_STR) * 4;
#pragma unroll
            for (int ks = 0; ks < 8; ks++) {
                uint32_t pf[4];
                ldsm4(pf, pbase + ks * 32 + lmP);
#pragma unroll
                for (int nt = 0; nt < 16; nt++) {
                    uint32_t b0 = __float_as_uint(Vs[(ks * 8 + c4) * AQ_STR + nt * 8 + qr]);
                    uint32_t b1 = __float_as_uint(Vs[(ks * 8 + 4 + c4) * AQ_STR + nt * 8 + qr]);
                    mma_tf32(of[nt], pf, b0, b1);
                }
            }
        }
        __syncthreads();
    }

    // epilogue: write g_o already tf32-rounded (proj GEMM copies it raw)
    {
        float inv0 = 1.0f / l0, inv1 = 1.0f / l1;
        int r0 = q0 + w * 16 + qr;
        float* og0 = g_o + ((size_t)(b * L_) + r0) * DIM_ + h * HD_;
        float* og1 = og0 + (size_t)8 * DIM_;
#pragma unroll
        for (int nt = 0; nt < 16; nt++) {
            int d = nt * 8 + c4 * 2;
            *reinterpret_cast<float2*>(&og0[d]) = make_float2(
                __uint_as_float(f2tf(of[nt][0] * inv0)),
                __uint_as_float(f2tf(of[nt][1] * inv0)));
            *reinterpret_cast<float2*>(&og1[d]) = make_float2(
                __uint_as_float(f2tf(of[nt][2] * inv1)),
                __uint_as_float(f2tf(of[nt][3] * inv1)));
        }
    }
}

// ============================================================================
extern "C" void kernel_launch(void* const* d_in, const int* in_sizes, int n_in,
                              void* d_out, int out_size)
{
    const float* x       = (const float*)d_in[0];
    const float* pe      = (const float*)d_in[1];
    const float* Wqkv    = (const float*)d_in[2];
    const float* bqkv    = (const float*)d_in[3];
    const float* q_scale = (const float*)d_in[4];
    const float* k_scale = (const float*)d_in[5];
    const float* Wproj   = (const float*)d_in[6];
    const float* bproj   = (const float*)d_in[7];
    float* out = (float*)d_out;

    cudaFuncSetAttribute(gemm_mma<1>, cudaFuncAttributeMaxDynamicSharedMemorySize, GEMM_SMEM);
    cudaFuncSetAttribute(gemm_mma<0>, cudaFuncAttributeMaxDynamicSharedMemorySize, GEMM_SMEM);
    cudaFuncSetAttribute(attn_mma, cudaFuncAttributeMaxDynamicSharedMemorySize, ATTN_SMEM);

    // 0) pre-round x, Wqkv, Wproj to tf32 (RNA) in scratch
    {
        float* xr = nullptr; float* wq = nullptr; float* wp = nullptr;
        cudaGetSymbolAddress((void**)&xr, g_xr);
        cudaGetSymbolAddress((void**)&wq, g_wq);
        cudaGetSymbolAddress((void**)&wp, g_wp);
        int n4x = TOK * DIM_ / 4, n4q = N_QKV * DIM_ / 4, n4p = DIM_ * DIM_ / 4;
        round_tf32<<<(n4x + 255) / 256, 256>>>((const float4*)x, (float4*)xr, n4x);
        round_tf32<<<(n4q + 255) / 256, 256>>>((const float4*)Wqkv, (float4*)wq, n4q);
        round_tf32<<<(n4p + 255) / 256, 256>>>((const float4*)Wproj, (float4*)wp, n4p);
    }

    float* xr = nullptr; float* wq = nullptr; float* wp = nullptr; float* go = nullptr;
    cudaGetSymbolAddress((void**)&xr, g_xr);
    cudaGetSymbolAddress((void**)&wq, g_wq);
    cudaGetSymbolAddress((void**)&wp, g_wp);
    cudaGetSymbolAddress((void**)&go, g_o);

    // 1) QKV GEMM (cp.async + tf32 mma.sync) + scatter
    {
        dim3 grid(N_QKV / 128, TOK / 128);
        gemm_mma<1><<<grid, 256, GEMM_SMEM>>>(xr, wq, bqkv, nullptr, TOK, N_QKV, DIM_);
    }
    // 2) RMSNorm + RoPE
    {
        int rows = 2 * B_ * H_ * L_;
        rmsrope_kernel<<<rows / 8, 256>>>(pe, q_scale, k_scale);
    }
    // 3) flash attention (tf32 mma.sync)
    {
        dim3 grid(L_ / 128, H_, B_);
        attn_mma<<<grid, 256, ATTN_SMEM>>>();
    }
    // 4) output projection (cp.async + tf32 mma.sync)
    {
        dim3 grid(DIM_ / 128, TOK / 128);
        gemm_mma<0><<<grid, 256, GEMM_SMEM>>>(go, wp, bproj, out, TOK, DIM_, DIM_);
    }
}